// round 1
// baseline (speedup 1.0000x reference)
#include <cuda_runtime.h>

#define BB 16
#define NN 4096
#define SS 512
#define NSAMP 32
#define POS (NSAMP*SS)       // 16384 positions per batch
#define PTOT (BB*POS)        // 262144 total positions
#define R2 0.16f

// ---------------- scratch (device globals; no allocation allowed) ----------
__device__ float g_feat[BB*SS*NSAMP*6];     // [b][s][ns][6]
__device__ float g_x0[BB*64*POS];           // [b][c][ns*S+s]
__device__ float g_x1[BB*64*POS];
__device__ float g_x2[BB*128*POS];
__device__ float g_sum0[64], g_sq0[64], g_a0[64], g_c0[64];
__device__ float g_sum1[64], g_sq1[64], g_a1[64], g_c1[64];
__device__ float g_sum2[128], g_sq2[128], g_a2[128], g_c2[128];

// ---------------- zero stats (graph is replayed; must reset every launch) --
__global__ void zero_stats_kernel() {
    int t = threadIdx.x;
    if (t < 64) { g_sum0[t]=0.f; g_sq0[t]=0.f; g_sum1[t]=0.f; g_sq1[t]=0.f; }
    if (t < 128){ g_sum2[t]=0.f; g_sq2[t]=0.f; }
}

// ---------------- FPS: 16 blocks x 1024 threads, 4 points/thread -----------
__global__ __launch_bounds__(1024) void fps_kernel(const float* __restrict__ xyz,
                                                   float* __restrict__ out_xyz) {
    int b = blockIdx.x;
    int t = threadIdx.x;
    const float* xb = xyz + (size_t)b * 3 * NN;

    float px[4], py[4], pz[4], dist[4];
#pragma unroll
    for (int k = 0; k < 4; k++) {
        int i = t + k * 1024;
        px[k] = xb[i]; py[k] = xb[NN + i]; pz[k] = xb[2 * NN + i];
        dist[k] = 1e10f;
    }

    __shared__ float sv[32];
    __shared__ int   si[32];
    __shared__ int   sfar;
    int lane = t & 31, warp = t >> 5;
    int far = 0;

    for (int s = 0; s < SS; s++) {
        float cx = xb[far], cy = xb[NN + far], cz = xb[2 * NN + far];
        if (t == 0) {
            out_xyz[(b * 3 + 0) * SS + s] = cx;
            out_xyz[(b * 3 + 1) * SS + s] = cy;
            out_xyz[(b * 3 + 2) * SS + s] = cz;
        }
        float bv = -1.f; int bi = 0;
#pragma unroll
        for (int k = 0; k < 4; k++) {
            float dx = px[k] - cx, dy = py[k] - cy, dz = pz[k] - cz;
            float d = dx * dx + dy * dy + dz * dz;
            float nd = fminf(dist[k], d);
            dist[k] = nd;
            int i = t + k * 1024;
            if (nd > bv || (nd == bv && i < bi)) { bv = nd; bi = i; }
        }
        // warp argmax (first-index tie-break)
#pragma unroll
        for (int off = 16; off; off >>= 1) {
            float ov = __shfl_down_sync(0xffffffffu, bv, off);
            int   oi = __shfl_down_sync(0xffffffffu, bi, off);
            if (ov > bv || (ov == bv && oi < bi)) { bv = ov; bi = oi; }
        }
        if (lane == 0) { sv[warp] = bv; si[warp] = bi; }
        __syncthreads();
        if (warp == 0) {
            bv = sv[lane]; bi = si[lane];
#pragma unroll
            for (int off = 16; off; off >>= 1) {
                float ov = __shfl_down_sync(0xffffffffu, bv, off);
                int   oi = __shfl_down_sync(0xffffffffu, bi, off);
                if (ov > bv || (ov == bv && oi < bi)) { bv = ov; bi = oi; }
            }
            if (lane == 0) sfar = bi;
        }
        __syncthreads();
        far = sfar;
    }
}

// ---------------- ball query + feature build -------------------------------
// grid (16, 4): block = (batch, chunk of 128 centroids), 1024 threads = 32 warps
// warp handles 4 centroids; shared: xyz(3) + |p|^2 + points(3) = 7*4096 floats
__global__ __launch_bounds__(1024) void ball_kernel(const float* __restrict__ xyz,
                                                    const float* __restrict__ pts,
                                                    const float* __restrict__ new_xyz) {
    extern __shared__ float sh[];
    float* sx  = sh;
    float* sy  = sh + NN;
    float* sz  = sh + 2 * NN;
    float* spp = sh + 3 * NN;
    float* sp0 = sh + 4 * NN;
    float* sp1 = sh + 5 * NN;
    float* sp2 = sh + 6 * NN;

    int b = blockIdx.x, chunk = blockIdx.y;
    int t = threadIdx.x;
    const float* xb = xyz + (size_t)b * 3 * NN;
    const float* pb = pts + (size_t)b * 3 * NN;

    for (int i = t; i < NN; i += 1024) {
        float x = xb[i], y = xb[NN + i], z = xb[2 * NN + i];
        sx[i] = x; sy[i] = y; sz[i] = z;
        spp[i] = x * x + y * y + z * z;
        sp0[i] = pb[i]; sp1[i] = pb[NN + i]; sp2[i] = pb[2 * NN + i];
    }
    __syncthreads();

    int lane = t & 31, warp = t >> 5;
    for (int q = 0; q < 4; q++) {
        int s = chunk * 128 + q * 32 + warp;
        float cx = new_xyz[(b * 3 + 0) * SS + s];
        float cy = new_xyz[(b * 3 + 1) * SS + s];
        float cz = new_xyz[(b * 3 + 2) * SS + s];
        float cc = cx * cx + cy * cy + cz * cz;

        int count = 0;
        int first_i = 0;
        for (int base = 0; base < NN; base += 32) {
            int i = base + lane;
            float dot = cx * sx[i] + cy * sy[i] + cz * sz[i];
            float sum2 = __fadd_rn(cc, spp[i]);
            float sqr = __fsub_rn(sum2, 2.0f * dot);
            bool pred = (sqr <= R2);
            unsigned mask = __ballot_sync(0xffffffffu, pred);
            if (count == 0 && mask) {
                int src = __ffs(mask) - 1;
                first_i = __shfl_sync(0xffffffffu, i, src);
            }
            int rank = __popc(mask & ((1u << lane) - 1u));
            int slot = count + rank;
            if (pred && slot < NSAMP) {
                size_t fb = ((size_t)(b * SS + s) * NSAMP + slot) * 6;
                g_feat[fb + 0] = sx[i] - cx;
                g_feat[fb + 1] = sy[i] - cy;
                g_feat[fb + 2] = sz[i] - cz;
                g_feat[fb + 3] = sp0[i];
                g_feat[fb + 4] = sp1[i];
                g_feat[fb + 5] = sp2[i];
            }
            count += __popc(mask);
            if (count >= NSAMP) break;
        }
        if (count < NSAMP && lane >= count) {
            int i = first_i;
            size_t fb = ((size_t)(b * SS + s) * NSAMP + lane) * 6;
            g_feat[fb + 0] = sx[i] - cx;
            g_feat[fb + 1] = sy[i] - cy;
            g_feat[fb + 2] = sz[i] - cz;
            g_feat[fb + 3] = sp0[i];
            g_feat[fb + 4] = sp1[i];
            g_feat[fb + 5] = sp2[i];
        }
    }
}

// ---------------- layer GEMM + stats ---------------------------------------
// x_raw = W * relu(a_prev * x_prev + c_prev) + bias ; accumulate sum/sumsq.
template <int L>
__global__ __launch_bounds__(256, 2) void layer_kernel(const float* __restrict__ w,
                                                       const float* __restrict__ bias) {
    constexpr int CIN  = (L == 0) ? 6 : 64;
    constexpr int COUT = (L == 2) ? 128 : 64;
    constexpr int TP   = (L == 2) ? 128 : 256;
    constexpr int OT   = COUT / 8;   // outputs per thread
    constexpr int PT   = TP / 32;    // positions per thread (4 or 8)

    extern __shared__ float sh[];
    float* sw = sh;                  // [CIN][COUT]
    float* sy = sh + CIN * COUT;     // [CIN][TP]

    int t = threadIdx.x;
    int bid = blockIdx.x;
    const int bpb = POS / TP;
    int b = bid / bpb;
    int p0 = (bid - b * bpb) * TP;

    for (int e = t; e < CIN * COUT; e += 256) {
        int o = e / CIN, c = e - o * CIN;
        sw[c * COUT + o] = w[e];
    }

    const float* xin = nullptr; const float* an = nullptr; const float* cn = nullptr;
    if (L == 1) { xin = g_x0; an = g_a0; cn = g_c0; }
    if (L == 2) { xin = g_x1; an = g_a1; cn = g_c1; }

    for (int e = t; e < CIN * TP; e += 256) {
        int c = e / TP, p = e - c * TP;
        float v;
        if (L == 0) {
            int pos = p0 + p;
            int ns = pos >> 9, s = pos & 511;
            v = g_feat[((size_t)(b * SS + s) * NSAMP + ns) * 6 + c];
        } else {
            v = xin[(size_t)(b * CIN + c) * POS + p0 + p];
            v = fmaxf(0.f, an[c] * v + cn[c]);
        }
        sy[c * TP + p] = v;
    }
    __syncthreads();

    int tx = t & 31, tg = t >> 5;
    float acc[OT][PT];
#pragma unroll
    for (int j = 0; j < OT; j++)
#pragma unroll
        for (int k = 0; k < PT; k++) acc[j][k] = 0.f;

#pragma unroll 4
    for (int c = 0; c < CIN; c++) {
        float wv[OT];
        const float4* wr = (const float4*)&sw[c * COUT + tg * OT];
#pragma unroll
        for (int j4 = 0; j4 < OT / 4; j4++) {
            float4 wq = wr[j4];
            wv[j4 * 4 + 0] = wq.x; wv[j4 * 4 + 1] = wq.y;
            wv[j4 * 4 + 2] = wq.z; wv[j4 * 4 + 3] = wq.w;
        }
        float4 y0 = *(const float4*)&sy[c * TP + tx * 4];
        float4 y1 = make_float4(0.f, 0.f, 0.f, 0.f);
        if (PT == 8) y1 = *(const float4*)&sy[c * TP + 128 + tx * 4];
#pragma unroll
        for (int j = 0; j < OT; j++) {
            float wj = wv[j];
            acc[j][0] += wj * y0.x; acc[j][1] += wj * y0.y;
            acc[j][2] += wj * y0.z; acc[j][3] += wj * y0.w;
            if (PT == 8) {
                acc[j][4] += wj * y1.x; acc[j][5] += wj * y1.y;
                acc[j][6] += wj * y1.z; acc[j][7] += wj * y1.w;
            }
        }
    }

    float* xout = (L == 0) ? g_x0 : (L == 1) ? g_x1 : g_x2;
    float* gsum = (L == 0) ? g_sum0 : (L == 1) ? g_sum1 : g_sum2;
    float* gsq  = (L == 0) ? g_sq0  : (L == 1) ? g_sq1  : g_sq2;

#pragma unroll
    for (int j = 0; j < OT; j++) {
        int o = tg * OT + j;
        float bo = bias[o];
        float s = 0.f, q = 0.f;
        float4 v0;
        v0.x = acc[j][0] + bo; v0.y = acc[j][1] + bo;
        v0.z = acc[j][2] + bo; v0.w = acc[j][3] + bo;
        *(float4*)&xout[(size_t)(b * COUT + o) * POS + p0 + tx * 4] = v0;
        s += v0.x + v0.y + v0.z + v0.w;
        q += v0.x * v0.x + v0.y * v0.y + v0.z * v0.z + v0.w * v0.w;
        if (PT == 8) {
            float4 v1;
            v1.x = acc[j][4] + bo; v1.y = acc[j][5] + bo;
            v1.z = acc[j][6] + bo; v1.w = acc[j][7] + bo;
            *(float4*)&xout[(size_t)(b * COUT + o) * POS + p0 + 128 + tx * 4] = v1;
            s += v1.x + v1.y + v1.z + v1.w;
            q += v1.x * v1.x + v1.y * v1.y + v1.z * v1.z + v1.w * v1.w;
        }
#pragma unroll
        for (int off = 16; off; off >>= 1) {
            s += __shfl_xor_sync(0xffffffffu, s, off);
            q += __shfl_xor_sync(0xffffffffu, q, off);
        }
        if (tx == 0) { atomicAdd(&gsum[o], s); atomicAdd(&gsq[o], q); }
    }
}

// ---------------- finalize: (sum,sumsq) -> affine (a,c) --------------------
template <int L>
__global__ void finalize_kernel(const float* __restrict__ g, const float* __restrict__ beta) {
    constexpr int C = (L == 2) ? 128 : 64;
    int o = threadIdx.x;
    if (o < C) {
        const float* sum = (L == 0) ? g_sum0 : (L == 1) ? g_sum1 : g_sum2;
        const float* sq  = (L == 0) ? g_sq0  : (L == 1) ? g_sq1  : g_sq2;
        float* a = (L == 0) ? g_a0 : (L == 1) ? g_a1 : g_a2;
        float* c = (L == 0) ? g_c0 : (L == 1) ? g_c1 : g_c2;
        const float invP = 1.0f / (float)PTOT;
        float m = sum[o] * invP;
        float v = sq[o] * invP - m * m;
        float av = g[o] * rsqrtf(v + 1e-5f);
        a[o] = av;
        c[o] = beta[o] - m * av;
    }
}

// ---------------- max over neighbors + final relu --------------------------
__global__ __launch_bounds__(256) void maxpool_kernel(float* __restrict__ out) {
    int idx = blockIdx.x * 256 + threadIdx.x;   // (b,o,s), 16*128*512 total
    int s = idx & 511;
    int o = (idx >> 9) & 127;
    int b = idx >> 16;
    const float* p = g_x2 + (size_t)(b * 128 + o) * POS + s;
    float av = g_a2[o], cv = g_c2[o];
    float m = -1e30f;
#pragma unroll
    for (int ns = 0; ns < NSAMP; ns++)
        m = fmaxf(m, av * p[ns * SS] + cv);
    out[BB * 3 * SS + idx] = fmaxf(m, 0.f);
}

// ---------------- launch ----------------------------------------------------
extern "C" void kernel_launch(void* const* d_in, const int* in_sizes, int n_in,
                              void* d_out, int out_size) {
    const float* xyz   = (const float*)d_in[0];
    const float* pts   = (const float*)d_in[1];
    const float* w0    = (const float*)d_in[2];
    const float* b0    = (const float*)d_in[3];
    const float* g0    = (const float*)d_in[4];
    const float* beta0 = (const float*)d_in[5];
    const float* w1    = (const float*)d_in[6];
    const float* b1    = (const float*)d_in[7];
    const float* g1    = (const float*)d_in[8];
    const float* beta1 = (const float*)d_in[9];
    const float* w2    = (const float*)d_in[10];
    const float* b2    = (const float*)d_in[11];
    const float* g2    = (const float*)d_in[12];
    const float* beta2 = (const float*)d_in[13];
    float* out = (float*)d_out;

    cudaFuncSetAttribute(ball_kernel, cudaFuncAttributeMaxDynamicSharedMemorySize, 7 * NN * 4);
    cudaFuncSetAttribute(layer_kernel<1>, cudaFuncAttributeMaxDynamicSharedMemorySize,
                         (64 * 64 + 64 * 256) * 4);
    cudaFuncSetAttribute(layer_kernel<2>, cudaFuncAttributeMaxDynamicSharedMemorySize,
                         (64 * 128 + 64 * 128) * 4);

    zero_stats_kernel<<<1, 128>>>();
    fps_kernel<<<BB, 1024>>>(xyz, out);
    ball_kernel<<<dim3(BB, 4), 1024, 7 * NN * 4>>>(xyz, pts, out);

    layer_kernel<0><<<BB * (POS / 256), 256, (6 * 64 + 6 * 256) * 4>>>(w0, b0);
    finalize_kernel<0><<<1, 64>>>(g0, beta0);
    layer_kernel<1><<<BB * (POS / 256), 256, (64 * 64 + 64 * 256) * 4>>>(w1, b1);
    finalize_kernel<1><<<1, 64>>>(g1, beta1);
    layer_kernel<2><<<BB * (POS / 128), 256, (64 * 128 + 64 * 128) * 4>>>(w2, b2);
    finalize_kernel<2><<<1, 128>>>(g2, beta2);

    maxpool_kernel<<<(BB * 128 * SS) / 256, 256>>>(out);
}

// round 2
// speedup vs baseline: 1.0244x; 1.0244x over previous
#include <cuda_runtime.h>

#define BB 16
#define NN 4096
#define SS 512
#define NSAMP 32
#define POS (NSAMP*SS)       // 16384 positions per batch; pos = s*32 + ns
#define PTOT (BB*POS)
#define R2 0.16f

// ---------------- scratch (device globals; no allocation allowed) ----------
__device__ float g_feat[BB*POS*6];          // [b][pos][6], pos = s*32+ns
__device__ float g_x0[BB*64*POS];           // [b][c][pos]
__device__ float g_x1[BB*64*POS];
__device__ float g_gmax[BB*128*SS];         // [b][o][s]
__device__ float g_gmin[BB*128*SS];
__device__ float g_sum0[64], g_sq0[64], g_a0[64], g_c0[64];
__device__ float g_sum1[64], g_sq1[64], g_a1[64], g_c1[64];
__device__ float g_sum2[128], g_sq2[128], g_a2[128], g_c2[128];

// ---------------- zero stats (graph replay: reset every launch) ------------
__global__ void zero_stats_kernel() {
    int t = threadIdx.x;
    if (t < 64) { g_sum0[t]=0.f; g_sq0[t]=0.f; g_sum1[t]=0.f; g_sq1[t]=0.f; }
    if (t < 128){ g_sum2[t]=0.f; g_sq2[t]=0.f; }
}

// ---------------- FPS: 16 blocks x 1024 threads, 4 pts/thread --------------
// Per step: update dists -> warp redux (u32 max + min-index) -> STS64 ->
// one barrier -> all warps redundantly reduce 32 entries -> next far.
// u32 compare == f32 compare for non-negative floats (bit-pattern monotone).
extern "C" __global__ __launch_bounds__(1024)
void fps_kernel(const float* __restrict__ xyz, float* __restrict__ out_xyz) {
    extern __shared__ float fsh[];
    float* sx = fsh;
    float* sy = fsh + NN;
    float* sz = fsh + 2 * NN;
    unsigned long long* sred = (unsigned long long*)(fsh + 3 * NN); // [2][32]

    int b = blockIdx.x, t = threadIdx.x, lane = t & 31, warp = t >> 5;
    const float* xb = xyz + (size_t)b * 3 * NN;

    float px[4], py[4], pz[4], dist[4];
#pragma unroll
    for (int k = 0; k < 4; k++) {
        int i = t + k * 1024;
        float x = xb[i], y = xb[NN + i], z = xb[2 * NN + i];
        px[k] = x; py[k] = y; pz[k] = z;
        sx[i] = x; sy[i] = y; sz[i] = z;
        dist[k] = 1e10f;
    }
    __syncthreads();

    int far = 0;
    for (int s = 0; s < SS; s++) {
        float cx = sx[far], cy = sy[far], cz = sz[far];
        if (t == 0) {
            out_xyz[(b * 3 + 0) * SS + s] = cx;
            out_xyz[(b * 3 + 1) * SS + s] = cy;
            out_xyz[(b * 3 + 2) * SS + s] = cz;
        }
        float bv; int bi;
        {
            float dx = px[0]-cx, dy = py[0]-cy, dz = pz[0]-cz;
            float d = dx*dx + dy*dy + dz*dz;
            float nd = fminf(dist[0], d); dist[0] = nd;
            bv = nd; bi = t;
        }
#pragma unroll
        for (int k = 1; k < 4; k++) {
            float dx = px[k]-cx, dy = py[k]-cy, dz = pz[k]-cz;
            float d = dx*dx + dy*dy + dz*dz;
            float nd = fminf(dist[k], d); dist[k] = nd;
            if (nd > bv) { bv = nd; bi = t + k * 1024; }
        }
        unsigned uv = __float_as_uint(bv);
        unsigned wm = __reduce_max_sync(0xffffffffu, uv);
        unsigned cand = (uv == wm) ? (unsigned)bi : 0xffffffffu;
        unsigned wi = __reduce_min_sync(0xffffffffu, cand);
        if (lane == 0)
            sred[(s & 1) * 32 + warp] = ((unsigned long long)wm << 32) | wi;
        __syncthreads();
        unsigned long long e = sred[(s & 1) * 32 + lane];
        unsigned v = (unsigned)(e >> 32), ix = (unsigned)e;
        unsigned m2 = __reduce_max_sync(0xffffffffu, v);
        unsigned c2 = (v == m2) ? ix : 0xffffffffu;
        far = (int)__reduce_min_sync(0xffffffffu, c2);
    }
}

// ---------------- ball query + feature build -------------------------------
// grid (16, 8): (batch, chunk of 64 centroids), 1024 threads; warp: 2 centroids
extern "C" __global__ __launch_bounds__(1024)
void ball_kernel(const float* __restrict__ xyz, const float* __restrict__ pts,
                 const float* __restrict__ new_xyz) {
    extern __shared__ float sh[];
    float* sx  = sh;
    float* sy  = sh + NN;
    float* sz  = sh + 2 * NN;
    float* spp = sh + 3 * NN;
    float* sp0 = sh + 4 * NN;
    float* sp1 = sh + 5 * NN;
    float* sp2 = sh + 6 * NN;

    int b = blockIdx.x, chunk = blockIdx.y;
    int t = threadIdx.x;
    const float* xb = xyz + (size_t)b * 3 * NN;
    const float* pb = pts + (size_t)b * 3 * NN;

    for (int i = t; i < NN; i += 1024) {
        float x = xb[i], y = xb[NN + i], z = xb[2 * NN + i];
        sx[i] = x; sy[i] = y; sz[i] = z;
        spp[i] = x * x + y * y + z * z;
        sp0[i] = pb[i]; sp1[i] = pb[NN + i]; sp2[i] = pb[2 * NN + i];
    }
    __syncthreads();

    int lane = t & 31, warp = t >> 5;
    for (int q = 0; q < 2; q++) {
        int s = chunk * 64 + q * 32 + warp;
        float cx = new_xyz[(b * 3 + 0) * SS + s];
        float cy = new_xyz[(b * 3 + 1) * SS + s];
        float cz = new_xyz[(b * 3 + 2) * SS + s];
        float cc = cx * cx + cy * cy + cz * cz;

        int count = 0;
        int first_i = 0;
        for (int base = 0; base < NN; base += 32) {
            int i = base + lane;
            float dot = cx * sx[i] + cy * sy[i] + cz * sz[i];
            float sum2 = __fadd_rn(cc, spp[i]);
            float sqr = __fsub_rn(sum2, 2.0f * dot);
            bool pred = (sqr <= R2);
            unsigned mask = __ballot_sync(0xffffffffu, pred);
            if (count == 0 && mask) {
                int src = __ffs(mask) - 1;
                first_i = __shfl_sync(0xffffffffu, i, src);
            }
            int rank = __popc(mask & ((1u << lane) - 1u));
            int slot = count + rank;
            if (pred && slot < NSAMP) {
                size_t fb = ((size_t)b * POS + (size_t)s * NSAMP + slot) * 6;
                g_feat[fb + 0] = sx[i] - cx;
                g_feat[fb + 1] = sy[i] - cy;
                g_feat[fb + 2] = sz[i] - cz;
                g_feat[fb + 3] = sp0[i];
                g_feat[fb + 4] = sp1[i];
                g_feat[fb + 5] = sp2[i];
            }
            count += __popc(mask);
            if (count >= NSAMP) break;
        }
        if (count < NSAMP && lane >= count) {
            int i = first_i;
            size_t fb = ((size_t)b * POS + (size_t)s * NSAMP + lane) * 6;
            g_feat[fb + 0] = sx[i] - cx;
            g_feat[fb + 1] = sy[i] - cy;
            g_feat[fb + 2] = sz[i] - cz;
            g_feat[fb + 3] = sp0[i];
            g_feat[fb + 4] = sp1[i];
            g_feat[fb + 5] = sp2[i];
        }
    }
}

// ---------------- layer GEMM + stats (+fused neighbor max/min for L2) ------
template <int L>
__global__ __launch_bounds__(256, 3) void layer_kernel(const float* __restrict__ w,
                                                       const float* __restrict__ bias) {
    constexpr int CIN  = (L == 0) ? 6 : 64;
    constexpr int COUT = (L == 2) ? 128 : 64;
    constexpr int TP   = (L == 2) ? 64 : 128;
    constexpr int PT   = TP / 32;          // 2 or 4
    constexpr int OT   = COUT / 8;         // 16 or 8 (8 warps)

    extern __shared__ float sh[];
    float* sw = sh;                  // [CIN][COUT]
    float* sy = sh + CIN * COUT;     // [CIN][TP]

    int t = threadIdx.x;
    int bid = blockIdx.x;
    const int bpb = POS / TP;
    int b = bid / bpb;
    int p0 = (bid - b * bpb) * TP;

    for (int e = t; e < CIN * COUT; e += 256) {
        int o = e / CIN, c = e - o * CIN;
        sw[c * COUT + o] = w[e];
    }

    const float* xin = nullptr; const float* an = nullptr; const float* cn = nullptr;
    if (L == 1) { xin = g_x0; an = g_a0; cn = g_c0; }
    if (L == 2) { xin = g_x1; an = g_a1; cn = g_c1; }

    if (L == 0) {
        for (int e = t; e < CIN * TP; e += 256) {
            int p = e / 6, c = e - p * 6;
            sy[c * TP + p] = g_feat[((size_t)b * POS + p0 + p) * 6 + c];
        }
    } else {
        for (int e = t; e < CIN * TP; e += 256) {
            int c = e / TP, p = e - c * TP;
            float v = xin[(size_t)(b * CIN + c) * POS + p0 + p];
            sy[c * TP + p] = fmaxf(0.f, an[c] * v + cn[c]);
        }
    }
    __syncthreads();

    int tx = t & 31, tg = t >> 5;
    float acc[OT][PT];
#pragma unroll
    for (int j = 0; j < OT; j++)
#pragma unroll
        for (int k = 0; k < PT; k++) acc[j][k] = 0.f;

#pragma unroll 2
    for (int c = 0; c < CIN; c++) {
        float wv[OT];
        const float4* wr = (const float4*)&sw[c * COUT + tg * OT];
#pragma unroll
        for (int j4 = 0; j4 < OT / 4; j4++) {
            float4 wq = wr[j4];
            wv[j4*4+0] = wq.x; wv[j4*4+1] = wq.y; wv[j4*4+2] = wq.z; wv[j4*4+3] = wq.w;
        }
        float yv[PT];
        if (PT == 4) {
            float4 y0 = *(const float4*)&sy[c * TP + tx * 4];
            yv[0] = y0.x; yv[1] = y0.y; yv[2] = y0.z; yv[3] = y0.w;
        } else {
            float2 y0 = *(const float2*)&sy[c * TP + tx * 2];
            yv[0] = y0.x; yv[1] = y0.y;
        }
#pragma unroll
        for (int j = 0; j < OT; j++)
#pragma unroll
            for (int k = 0; k < PT; k++)
                acc[j][k] += wv[j] * yv[k];
    }

    float* xout = (L == 0) ? g_x0 : g_x1;
    float* gsum = (L == 0) ? g_sum0 : (L == 1) ? g_sum1 : g_sum2;
    float* gsq  = (L == 0) ? g_sq0  : (L == 1) ? g_sq1  : g_sq2;

#pragma unroll
    for (int j = 0; j < OT; j++) {
        int o = tg * OT + j;
        float bo = bias[o];
        float v[PT];
        float s = 0.f, q = 0.f;
#pragma unroll
        for (int k = 0; k < PT; k++) {
            v[k] = acc[j][k] + bo;
            s += v[k];
            q += v[k] * v[k];
        }
        if (L < 2) {
            float4 v4; v4.x = v[0]; v4.y = v[1]; v4.z = v[2]; v4.w = v[3];
            *(float4*)&xout[(size_t)(b * COUT + o) * POS + p0 + tx * 4] = v4;
        } else {
            // neighbor max/min over ns: 32 consecutive pos = 16 lanes (PT=2)
            float mx = fmaxf(v[0], v[1]);
            float mn = fminf(v[0], v[1]);
#pragma unroll
            for (int off = 1; off < 16; off <<= 1) {
                mx = fmaxf(mx, __shfl_xor_sync(0xffffffffu, mx, off));
                mn = fminf(mn, __shfl_xor_sync(0xffffffffu, mn, off));
            }
            if ((tx & 15) == 0) {
                int sgrp = (p0 >> 5) + (tx >> 4);
                g_gmax[(size_t)(b * 128 + o) * SS + sgrp] = mx;
                g_gmin[(size_t)(b * 128 + o) * SS + sgrp] = mn;
            }
        }
#pragma unroll
        for (int off = 16; off; off >>= 1) {
            s += __shfl_xor_sync(0xffffffffu, s, off);
            q += __shfl_xor_sync(0xffffffffu, q, off);
        }
        if (tx == 0) { atomicAdd(&gsum[o], s); atomicAdd(&gsq[o], q); }
    }
}

// ---------------- finalize: (sum,sumsq) -> affine (a,c) --------------------
template <int L>
__global__ void finalize_kernel(const float* __restrict__ g, const float* __restrict__ beta) {
    constexpr int C = (L == 2) ? 128 : 64;
    int o = threadIdx.x;
    if (o < C) {
        const float* sum = (L == 0) ? g_sum0 : (L == 1) ? g_sum1 : g_sum2;
        const float* sq  = (L == 0) ? g_sq0  : (L == 1) ? g_sq1  : g_sq2;
        float* a = (L == 0) ? g_a0 : (L == 1) ? g_a1 : g_a2;
        float* c = (L == 0) ? g_c0 : (L == 1) ? g_c1 : g_c2;
        const float invP = 1.0f / (float)PTOT;
        float m = sum[o] * invP;
        float v = sq[o] * invP - m * m;
        float av = g[o] * rsqrtf(v + 1e-5f);
        a[o] = av;
        c[o] = beta[o] - m * av;
    }
}

// ---------------- final: affine + relu on pooled raw max/min ---------------
// a>=0: max over ns of (a*x+c) = a*max(x)+c ; a<0: = a*min(x)+c (monotone)
__global__ __launch_bounds__(256) void final_kernel(float* __restrict__ out) {
    int idx = blockIdx.x * 256 + threadIdx.x;   // (b,o,s)
    int o = (idx >> 9) & 127;
    float a = g_a2[o], c = g_c2[o];
    float m = (a >= 0.f) ? g_gmax[idx] : g_gmin[idx];
    out[BB * 3 * SS + idx] = fmaxf(a * m + c, 0.f);
}

// ---------------- launch ----------------------------------------------------
extern "C" void kernel_launch(void* const* d_in, const int* in_sizes, int n_in,
                              void* d_out, int out_size) {
    const float* xyz   = (const float*)d_in[0];
    const float* pts   = (const float*)d_in[1];
    const float* w0    = (const float*)d_in[2];
    const float* b0    = (const float*)d_in[3];
    const float* g0    = (const float*)d_in[4];
    const float* beta0 = (const float*)d_in[5];
    const float* w1    = (const float*)d_in[6];
    const float* b1    = (const float*)d_in[7];
    const float* g1    = (const float*)d_in[8];
    const float* beta1 = (const float*)d_in[9];
    const float* w2    = (const float*)d_in[10];
    const float* b2    = (const float*)d_in[11];
    const float* g2    = (const float*)d_in[12];
    const float* beta2 = (const float*)d_in[13];
    float* out = (float*)d_out;

    cudaFuncSetAttribute(fps_kernel, cudaFuncAttributeMaxDynamicSharedMemorySize,
                         3 * NN * 4 + 512);
    cudaFuncSetAttribute(ball_kernel, cudaFuncAttributeMaxDynamicSharedMemorySize,
                         7 * NN * 4);
    cudaFuncSetAttribute(layer_kernel<1>, cudaFuncAttributeMaxDynamicSharedMemorySize,
                         (64 * 64 + 64 * 128) * 4);
    cudaFuncSetAttribute(layer_kernel<2>, cudaFuncAttributeMaxDynamicSharedMemorySize,
                         (64 * 128 + 64 * 64) * 4);

    zero_stats_kernel<<<1, 128>>>();
    fps_kernel<<<BB, 1024, 3 * NN * 4 + 512>>>(xyz, out);
    ball_kernel<<<dim3(BB, 8), 1024, 7 * NN * 4>>>(xyz, pts, out);

    layer_kernel<0><<<BB * (POS / 128), 256, (6 * 64 + 6 * 128) * 4>>>(w0, b0);
    finalize_kernel<0><<<1, 64>>>(g0, beta0);
    layer_kernel<1><<<BB * (POS / 128), 256, (64 * 64 + 64 * 128) * 4>>>(w1, b1);
    finalize_kernel<1><<<1, 64>>>(g1, beta1);
    layer_kernel<2><<<BB * (POS / 64), 256, (64 * 128 + 64 * 64) * 4>>>(w2, b2);
    finalize_kernel<2><<<1, 128>>>(g2, beta2);

    final_kernel<<<(BB * 128 * SS) / 256, 256>>>(out);
}

// round 3
// speedup vs baseline: 1.8742x; 1.8294x over previous
#include <cuda_runtime.h>

#define BB 16
#define NN 4096
#define SS 512
#define NSAMP 32
#define POS (NSAMP*SS)       // 16384 positions per batch; pos = s*32 + ns
#define PTOT (BB*POS)
#define R2 0.16f

// ---------------- scratch (device globals; no allocation allowed) ----------
__device__ float g_x0[BB*64*POS];           // [b][c][pos] raw W0*feat (no bias)
__device__ float g_x1[BB*64*POS];           // raw W1*y1
__device__ float g_gmax[BB*128*SS];         // [b][o][s]
__device__ float g_gmin[BB*128*SS];
__device__ float g_fs[6], g_gm[21];         // feat sums + Gram (layer0 stats)
__device__ float g_a0[64], g_c0[64];
__device__ float g_sum1[64], g_sq1[64], g_a1[64], g_c1[64];
__device__ float g_sum2[128], g_sq2[128], g_a2[128], g_c2[128];

// ---------------- zero stats (graph replay: reset every launch) ------------
__global__ void zero_stats_kernel() {
    int t = threadIdx.x;
    if (t < 27) { if (t < 21) g_gm[t] = 0.f; else g_fs[t - 21] = 0.f; }
    if (t < 64) { g_sum1[t] = 0.f; g_sq1[t] = 0.f; }
    if (t < 128){ g_sum2[t] = 0.f; g_sq2[t] = 0.f; }
}

// ---------------- FPS: 16 blocks x 1024 threads, 4 pts/thread --------------
extern "C" __global__ __launch_bounds__(1024)
void fps_kernel(const float* __restrict__ xyz, float* __restrict__ out_xyz) {
    extern __shared__ float fsh[];
    float* sx = fsh;
    float* sy = fsh + NN;
    float* sz = fsh + 2 * NN;
    unsigned long long* sred = (unsigned long long*)(fsh + 3 * NN); // [2][32]

    int b = blockIdx.x, t = threadIdx.x, lane = t & 31, warp = t >> 5;
    const float* xb = xyz + (size_t)b * 3 * NN;

    float px[4], py[4], pz[4], dist[4];
#pragma unroll
    for (int k = 0; k < 4; k++) {
        int i = t + k * 1024;
        float x = xb[i], y = xb[NN + i], z = xb[2 * NN + i];
        px[k] = x; py[k] = y; pz[k] = z;
        sx[i] = x; sy[i] = y; sz[i] = z;
        dist[k] = 1e10f;
    }
    __syncthreads();

    int far = 0;
    for (int s = 0; s < SS; s++) {
        float cx = sx[far], cy = sy[far], cz = sz[far];
        if (t == 0) {
            out_xyz[(b * 3 + 0) * SS + s] = cx;
            out_xyz[(b * 3 + 1) * SS + s] = cy;
            out_xyz[(b * 3 + 2) * SS + s] = cz;
        }
        float bv; int bi;
        {
            float dx = px[0]-cx, dy = py[0]-cy, dz = pz[0]-cz;
            float d = dx*dx + dy*dy + dz*dz;
            float nd = fminf(dist[0], d); dist[0] = nd;
            bv = nd; bi = t;
        }
#pragma unroll
        for (int k = 1; k < 4; k++) {
            float dx = px[k]-cx, dy = py[k]-cy, dz = pz[k]-cz;
            float d = dx*dx + dy*dy + dz*dz;
            float nd = fminf(dist[k], d); dist[k] = nd;
            if (nd > bv) { bv = nd; bi = t + k * 1024; }
        }
        unsigned uv = __float_as_uint(bv);
        unsigned wm = __reduce_max_sync(0xffffffffu, uv);
        unsigned cand = (uv == wm) ? (unsigned)bi : 0xffffffffu;
        unsigned wi = __reduce_min_sync(0xffffffffu, cand);
        if (lane == 0)
            sred[(s & 1) * 32 + warp] = ((unsigned long long)wm << 32) | wi;
        __syncthreads();
        unsigned long long e = sred[(s & 1) * 32 + lane];
        unsigned v = (unsigned)(e >> 32), ix = (unsigned)e;
        unsigned m2 = __reduce_max_sync(0xffffffffu, v);
        unsigned c2 = (v == m2) ? ix : 0xffffffffu;
        far = (int)__reduce_min_sync(0xffffffffu, c2);
    }
}

// ---------------- ball query + fused layer0 + Gram stats -------------------
// grid (16, 8): (batch, chunk of 64 centroids), 1024 threads; warp: 2 centroids
// Writes x0 = W0 * feat directly (no g_feat round trip). Stats via 6x6 Gram.
#define BALL_SMEM_F (7*NN + 384 + 32*32*6 + 32*27)
extern "C" __global__ __launch_bounds__(1024)
void ball_kernel(const float* __restrict__ xyz, const float* __restrict__ pts,
                 const float* __restrict__ new_xyz, const float* __restrict__ w0) {
    extern __shared__ float sh[];
    float* sx   = sh;
    float* sy   = sh + NN;
    float* sz   = sh + 2 * NN;
    float* spp  = sh + 3 * NN;
    float* sp0  = sh + 4 * NN;
    float* sp1  = sh + 5 * NN;
    float* sp2  = sh + 6 * NN;
    float* sw   = sh + 7 * NN;            // [64][6] row-major (= w0)
    float* swf  = sw + 384;               // [32 warps][32 slots][6]
    float* sred = swf + 32 * 32 * 6;      // [32 warps][27]

    int b = blockIdx.x, chunk = blockIdx.y;
    int t = threadIdx.x;
    const float* xb = xyz + (size_t)b * 3 * NN;
    const float* pb = pts + (size_t)b * 3 * NN;

    if (t < 384) sw[t] = w0[t];
    for (int i = t; i < NN; i += 1024) {
        float x = xb[i], y = xb[NN + i], z = xb[2 * NN + i];
        sx[i] = x; sy[i] = y; sz[i] = z;
        spp[i] = x * x + y * y + z * z;
        sp0[i] = pb[i]; sp1[i] = pb[NN + i]; sp2[i] = pb[2 * NN + i];
    }
    __syncthreads();

    int lane = t & 31, warp = t >> 5;
    float* wslots = swf + warp * 192;

    float gm[21];
    float fs[6];
#pragma unroll
    for (int k = 0; k < 21; k++) gm[k] = 0.f;
#pragma unroll
    for (int k = 0; k < 6; k++) fs[k] = 0.f;

    float* x0b = g_x0 + (size_t)b * 64 * POS;

    for (int q = 0; q < 2; q++) {
        int s = chunk * 64 + q * 32 + warp;
        float cx = new_xyz[(b * 3 + 0) * SS + s];
        float cy = new_xyz[(b * 3 + 1) * SS + s];
        float cz = new_xyz[(b * 3 + 2) * SS + s];
        float cc = cx * cx + cy * cy + cz * cz;

        int count = 0;
        int first_i = 0;
        for (int base = 0; base < NN; base += 32) {
            int i = base + lane;
            float dot = cx * sx[i] + cy * sy[i] + cz * sz[i];
            float sum2 = __fadd_rn(cc, spp[i]);
            float sqr = __fsub_rn(sum2, 2.0f * dot);
            bool pred = (sqr <= R2);
            unsigned mask = __ballot_sync(0xffffffffu, pred);
            if (count == 0 && mask) {
                int src = __ffs(mask) - 1;
                first_i = __shfl_sync(0xffffffffu, i, src);
            }
            int rank = __popc(mask & ((1u << lane) - 1u));
            int slot = count + rank;
            if (pred && slot < NSAMP) {
                float* d = wslots + slot * 6;
                d[0] = sx[i] - cx; d[1] = sy[i] - cy; d[2] = sz[i] - cz;
                d[3] = sp0[i];     d[4] = sp1[i];     d[5] = sp2[i];
            }
            count += __popc(mask);
            if (count >= NSAMP) break;
        }
        if (count < NSAMP && lane >= count) {
            int i = first_i;
            float* d = wslots + lane * 6;
            d[0] = sx[i] - cx; d[1] = sy[i] - cy; d[2] = sz[i] - cz;
            d[3] = sp0[i];     d[4] = sp1[i];     d[5] = sp2[i];
        }
        __syncwarp();

        // each lane takes slot==lane: Gram + layer0 outputs
        float f[6];
#pragma unroll
        for (int c = 0; c < 6; c++) f[c] = wslots[lane * 6 + c];
        {
            int k = 0;
#pragma unroll
            for (int c = 0; c < 6; c++) {
                fs[c] += f[c];
#pragma unroll
                for (int d = c; d < 6; d++) gm[k++] += f[c] * f[d];
            }
        }
        float* xo = x0b + (size_t)s * 32 + lane;
#pragma unroll 8
        for (int o = 0; o < 64; o++) {
            const float2* wr = (const float2*)&sw[o * 6];
            float2 w01 = wr[0], w23 = wr[1], w45 = wr[2];
            float acc = w01.x * f[0] + w01.y * f[1] + w23.x * f[2]
                      + w23.y * f[3] + w45.x * f[4] + w45.y * f[5];
            xo[(size_t)o * POS] = acc;
        }
        __syncwarp();
    }

    // block-level reduce of Gram + fsum, then 27 atomics
#pragma unroll
    for (int k = 0; k < 21; k++)
#pragma unroll
        for (int off = 16; off; off >>= 1)
            gm[k] += __shfl_xor_sync(0xffffffffu, gm[k], off);
#pragma unroll
    for (int k = 0; k < 6; k++)
#pragma unroll
        for (int off = 16; off; off >>= 1)
            fs[k] += __shfl_xor_sync(0xffffffffu, fs[k], off);
    if (lane == 0) {
#pragma unroll
        for (int k = 0; k < 21; k++) sred[warp * 27 + k] = gm[k];
#pragma unroll
        for (int k = 0; k < 6; k++)  sred[warp * 27 + 21 + k] = fs[k];
    }
    __syncthreads();
    if (t < 27) {
        float v = 0.f;
#pragma unroll 8
        for (int w = 0; w < 32; w++) v += sred[w * 27 + t];
        if (t < 21) atomicAdd(&g_gm[t], v);
        else        atomicAdd(&g_fs[t - 21], v);
    }
}

// ---------------- finalize0: analytic stats from Gram ----------------------
__global__ void finalize0_kernel(const float* __restrict__ w0,
                                 const float* __restrict__ g0,
                                 const float* __restrict__ beta0) {
    __shared__ float G[36];
    __shared__ float F[6];
    int t = threadIdx.x;
    if (t < 36) {
        int c = t / 6, d = t % 6;
        int a = min(c, d), e = max(c, d);
        int k = a * 6 - a * (a + 1) / 2 + e;
        G[t] = g_gm[k];
    }
    if (t < 6) F[t] = g_fs[t];
    __syncthreads();
    if (t < 64) {
        float wv[6];
#pragma unroll
        for (int c = 0; c < 6; c++) wv[c] = w0[t * 6 + c];
        const float invP = 1.0f / (float)PTOT;
        float m = 0.f;
#pragma unroll
        for (int c = 0; c < 6; c++) m += wv[c] * F[c];
        m *= invP;
        float e2 = 0.f;
#pragma unroll
        for (int c = 0; c < 6; c++)
#pragma unroll
            for (int d = 0; d < 6; d++) e2 += wv[c] * wv[d] * G[c * 6 + d];
        e2 *= invP;
        float var = e2 - m * m;
        float a = g0[t] * rsqrtf(var + 1e-5f);
        g_a0[t] = a;
        g_c0[t] = beta0[t] - a * m;
    }
}

// ---------------- layer1: 64->64 GEMM, 4 tiles/block, deferred stats -------
extern "C" __global__ __launch_bounds__(256, 2)
void layer1_kernel(const float* __restrict__ w1) {
    extern __shared__ float sh[];
    float* sw = sh;            // [64][64]: sw[c*64+o]
    float* sy = sh + 4096;     // [64][256]
    __shared__ float san[64], scn[64];

    int t = threadIdx.x;
    int b = blockIdx.x >> 4, blk = blockIdx.x & 15;
    int lane = t & 31, tg = t >> 5;

    for (int e = t; e < 4096; e += 256) {
        int o = e >> 6, c = e & 63;
        sw[c * 64 + o] = w1[e];
    }
    if (t < 64) { san[t] = g_a0[t]; scn[t] = g_c0[t]; }

    const float* xin = g_x0 + (size_t)b * 64 * POS;
    float* xout = g_x1 + (size_t)b * 64 * POS;

    float s8[8], q8[8];
#pragma unroll
    for (int j = 0; j < 8; j++) { s8[j] = 0.f; q8[j] = 0.f; }

    for (int tile = 0; tile < 4; tile++) {
        int p0 = (blk * 4 + tile) * 256;
        __syncthreads();
        for (int e4 = t; e4 < 4096; e4 += 256) {
            int c = e4 >> 6, p4 = e4 & 63;
            float4 v = *(const float4*)&xin[(size_t)c * POS + p0 + p4 * 4];
            float a = san[c], cc = scn[c];
            v.x = fmaxf(0.f, a * v.x + cc);
            v.y = fmaxf(0.f, a * v.y + cc);
            v.z = fmaxf(0.f, a * v.z + cc);
            v.w = fmaxf(0.f, a * v.w + cc);
            *(float4*)&sy[c * 256 + p4 * 4] = v;
        }
        __syncthreads();

        float acc[8][8];
#pragma unroll
        for (int j = 0; j < 8; j++)
#pragma unroll
            for (int k = 0; k < 8; k++) acc[j][k] = 0.f;

#pragma unroll 8
        for (int c = 0; c < 64; c++) {
            float4 wa = *(const float4*)&sw[c * 64 + tg * 8];
            float4 wb = *(const float4*)&sw[c * 64 + tg * 8 + 4];
            float4 ya = *(const float4*)&sy[c * 256 + lane * 8];
            float4 yb = *(const float4*)&sy[c * 256 + lane * 8 + 4];
            float wv[8] = {wa.x, wa.y, wa.z, wa.w, wb.x, wb.y, wb.z, wb.w};
            float yv[8] = {ya.x, ya.y, ya.z, ya.w, yb.x, yb.y, yb.z, yb.w};
#pragma unroll
            for (int j = 0; j < 8; j++)
#pragma unroll
                for (int k = 0; k < 8; k++) acc[j][k] += wv[j] * yv[k];
        }

#pragma unroll
        for (int j = 0; j < 8; j++) {
            int o = tg * 8 + j;
            float4 v0, v1;
            v0.x = acc[j][0]; v0.y = acc[j][1]; v0.z = acc[j][2]; v0.w = acc[j][3];
            v1.x = acc[j][4]; v1.y = acc[j][5]; v1.z = acc[j][6]; v1.w = acc[j][7];
            *(float4*)&xout[(size_t)o * POS + p0 + lane * 8]     = v0;
            *(float4*)&xout[(size_t)o * POS + p0 + lane * 8 + 4] = v1;
            s8[j] += v0.x + v0.y + v0.z + v0.w + v1.x + v1.y + v1.z + v1.w;
            q8[j] += v0.x*v0.x + v0.y*v0.y + v0.z*v0.z + v0.w*v0.w
                   + v1.x*v1.x + v1.y*v1.y + v1.z*v1.z + v1.w*v1.w;
        }
    }

#pragma unroll
    for (int j = 0; j < 8; j++) {
#pragma unroll
        for (int off = 16; off; off >>= 1) {
            s8[j] += __shfl_xor_sync(0xffffffffu, s8[j], off);
            q8[j] += __shfl_xor_sync(0xffffffffu, q8[j], off);
        }
        if (lane == 0) {
            atomicAdd(&g_sum1[tg * 8 + j], s8[j]);
            atomicAdd(&g_sq1[tg * 8 + j],  q8[j]);
        }
    }
}

// ---------------- layer2: 64->128 GEMM + fused pool, 8 tiles/block ---------
extern "C" __global__ __launch_bounds__(256, 2)
void layer2_kernel(const float* __restrict__ w2) {
    extern __shared__ float sh[];
    float* sw = sh;            // [64][128]: sw[c*128+o]
    float* sy = sh + 8192;     // [64][128]
    __shared__ float san[64], scn[64];

    int t = threadIdx.x;
    int b = blockIdx.x >> 4, blk = blockIdx.x & 15;
    int lane = t & 31, tg = t >> 5;
    int o0 = tg * 16;

    for (int e = t; e < 8192; e += 256) {
        int o = e >> 6, c = e & 63;
        sw[c * 128 + o] = w2[e];
    }
    if (t < 64) { san[t] = g_a1[t]; scn[t] = g_c1[t]; }

    const float* xin = g_x1 + (size_t)b * 64 * POS;

    float s16[16], q16[16];
#pragma unroll
    for (int j = 0; j < 16; j++) { s16[j] = 0.f; q16[j] = 0.f; }

    for (int tile = 0; tile < 8; tile++) {
        int p0 = (blk * 8 + tile) * 128;
        __syncthreads();
        for (int e4 = t; e4 < 2048; e4 += 256) {
            int c = e4 >> 5, p4 = e4 & 31;
            float4 v = *(const float4*)&xin[(size_t)c * POS + p0 + p4 * 4];
            float a = san[c], cc = scn[c];
            v.x = fmaxf(0.f, a * v.x + cc);
            v.y = fmaxf(0.f, a * v.y + cc);
            v.z = fmaxf(0.f, a * v.z + cc);
            v.w = fmaxf(0.f, a * v.w + cc);
            *(float4*)&sy[c * 128 + p4 * 4] = v;
        }
        __syncthreads();

        float acc[16][4];
#pragma unroll
        for (int j = 0; j < 16; j++)
#pragma unroll
            for (int k = 0; k < 4; k++) acc[j][k] = 0.f;

#pragma unroll 4
        for (int c = 0; c < 64; c++) {
            float4 y = *(const float4*)&sy[c * 128 + lane * 4];
            float yv[4] = {y.x, y.y, y.z, y.w};
#pragma unroll
            for (int j4 = 0; j4 < 4; j4++) {
                float4 w = *(const float4*)&sw[c * 128 + o0 + j4 * 4];
                float wv[4] = {w.x, w.y, w.z, w.w};
#pragma unroll
                for (int jj = 0; jj < 4; jj++)
#pragma unroll
                    for (int k = 0; k < 4; k++)
                        acc[j4 * 4 + jj][k] += wv[jj] * yv[k];
            }
        }

        int sg = (p0 >> 5) + (lane >> 3);   // 4 s-groups per tile, 8 lanes each
#pragma unroll
        for (int j = 0; j < 16; j++) {
            int o = o0 + j;
            float v0 = acc[j][0], v1 = acc[j][1], v2 = acc[j][2], v3 = acc[j][3];
            s16[j] += v0 + v1 + v2 + v3;
            q16[j] += v0*v0 + v1*v1 + v2*v2 + v3*v3;
            float mx = fmaxf(fmaxf(v0, v1), fmaxf(v2, v3));
            float mn = fminf(fminf(v0, v1), fminf(v2, v3));
#pragma unroll
            for (int off = 1; off < 8; off <<= 1) {
                mx = fmaxf(mx, __shfl_xor_sync(0xffffffffu, mx, off));
                mn = fminf(mn, __shfl_xor_sync(0xffffffffu, mn, off));
            }
            if ((lane & 7) == 0) {
                g_gmax[(size_t)(b * 128 + o) * SS + sg] = mx;
                g_gmin[(size_t)(b * 128 + o) * SS + sg] = mn;
            }
        }
    }

#pragma unroll
    for (int j = 0; j < 16; j++) {
#pragma unroll
        for (int off = 16; off; off >>= 1) {
            s16[j] += __shfl_xor_sync(0xffffffffu, s16[j], off);
            q16[j] += __shfl_xor_sync(0xffffffffu, q16[j], off);
        }
        if (lane == 0) {
            atomicAdd(&g_sum2[o0 + j], s16[j]);
            atomicAdd(&g_sq2[o0 + j],  q16[j]);
        }
    }
}

// ---------------- finalize (layers 1/2): (sum,sumsq) -> affine -------------
template <int L>
__global__ void finalize_kernel(const float* __restrict__ g, const float* __restrict__ beta) {
    constexpr int C = (L == 2) ? 128 : 64;
    int o = threadIdx.x;
    if (o < C) {
        const float* sum = (L == 1) ? g_sum1 : g_sum2;
        const float* sq  = (L == 1) ? g_sq1  : g_sq2;
        float* a = (L == 1) ? g_a1 : g_a2;
        float* c = (L == 1) ? g_c1 : g_c2;
        const float invP = 1.0f / (float)PTOT;
        float m = sum[o] * invP;
        float v = sq[o] * invP - m * m;
        float av = g[o] * rsqrtf(v + 1e-5f);
        a[o] = av;
        c[o] = beta[o] - m * av;
    }
}

// ---------------- final: affine + relu on pooled raw max/min ---------------
__global__ __launch_bounds__(256) void final_kernel(float* __restrict__ out) {
    int idx = blockIdx.x * 256 + threadIdx.x;   // (b,o,s)
    int o = (idx >> 9) & 127;
    float a = g_a2[o], c = g_c2[o];
    float m = (a >= 0.f) ? g_gmax[idx] : g_gmin[idx];
    out[BB * 3 * SS + idx] = fmaxf(a * m + c, 0.f);
}

// ---------------- launch ----------------------------------------------------
extern "C" void kernel_launch(void* const* d_in, const int* in_sizes, int n_in,
                              void* d_out, int out_size) {
    const float* xyz   = (const float*)d_in[0];
    const float* pts   = (const float*)d_in[1];
    const float* w0    = (const float*)d_in[2];
    const float* g0    = (const float*)d_in[4];
    const float* beta0 = (const float*)d_in[5];
    const float* w1    = (const float*)d_in[6];
    const float* g1    = (const float*)d_in[8];
    const float* beta1 = (const float*)d_in[9];
    const float* w2    = (const float*)d_in[10];
    const float* g2    = (const float*)d_in[12];
    const float* beta2 = (const float*)d_in[13];
    float* out = (float*)d_out;

    cudaFuncSetAttribute(fps_kernel, cudaFuncAttributeMaxDynamicSharedMemorySize,
                         3 * NN * 4 + 512);
    cudaFuncSetAttribute(ball_kernel, cudaFuncAttributeMaxDynamicSharedMemorySize,
                         BALL_SMEM_F * 4);
    cudaFuncSetAttribute(layer1_kernel, cudaFuncAttributeMaxDynamicSharedMemorySize,
                         (4096 + 64 * 256) * 4);
    cudaFuncSetAttribute(layer2_kernel, cudaFuncAttributeMaxDynamicSharedMemorySize,
                         (8192 + 64 * 128) * 4);

    zero_stats_kernel<<<1, 128>>>();
    fps_kernel<<<BB, 1024, 3 * NN * 4 + 512>>>(xyz, out);
    ball_kernel<<<dim3(BB, 8), 1024, BALL_SMEM_F * 4>>>(xyz, pts, out, w0);
    finalize0_kernel<<<1, 64>>>(w0, g0, beta0);

    layer1_kernel<<<256, 256, (4096 + 64 * 256) * 4>>>(w1);
    finalize_kernel<1><<<1, 64>>>(g1, beta1);
    layer2_kernel<<<256, 256, (8192 + 64 * 128) * 4>>>(w2);
    finalize_kernel<2><<<1, 128>>>(g2, beta2);

    final_kernel<<<(BB * 128 * SS) / 256, 256>>>(out);
}

// round 6
// speedup vs baseline: 2.0966x; 1.1187x over previous
#include <cuda_runtime.h>
#include <cstdint>

#define BB 16
#define NN 4096
#define SS 512
#define NSAMP 32
#define POS (NSAMP*SS)       // 16384 positions per batch; pos = s*32 + ns
#define PTOT (BB*POS)
#define R2 0.16f

// ---------------- scratch (device globals; no allocation allowed) ----------
__device__ float g_x0[BB*POS*64];           // [b][pos][c]  raw W0*feat
__device__ float g_x1[BB*POS*64];           // [b][pos][c]  raw W1*y1
__device__ float g_gmax[BB*128*SS];         // [b][o][s]
__device__ float g_gmin[BB*128*SS];
__device__ float g_fs[6], g_gm[21];
__device__ float g_a0[64], g_c0[64];
__device__ float g_sum1[64], g_sq1[64], g_a1[64], g_c1[64];
__device__ float g_sum2[128], g_sq2[128], g_a2[128], g_c2[128];

// ---------------- small helpers --------------------------------------------
__device__ __forceinline__ uint32_t cvt_tf32(float f) {
    uint32_t r; asm("cvt.rna.tf32.f32 %0, %1;" : "=r"(r) : "f"(f)); return r;
}
__device__ __forceinline__ void mma_tf32(float d[4], const uint32_t a[4],
                                         const uint32_t b[2]) {
    asm volatile(
        "mma.sync.aligned.m16n8k8.row.col.f32.tf32.tf32.f32 "
        "{%0,%1,%2,%3}, {%4,%5,%6,%7}, {%8,%9}, {%0,%1,%2,%3};"
        : "+f"(d[0]), "+f"(d[1]), "+f"(d[2]), "+f"(d[3])
        : "r"(a[0]), "r"(a[1]), "r"(a[2]), "r"(a[3]), "r"(b[0]), "r"(b[1]));
}

// ---------------- zero stats (graph replay: reset every launch) ------------
__global__ void zero_stats_kernel() {
    int t = threadIdx.x;
    if (t < 27) { if (t < 21) g_gm[t] = 0.f; else g_fs[t - 21] = 0.f; }
    if (t < 64) { g_sum1[t] = 0.f; g_sq1[t] = 0.f; }
    if (t < 128){ g_sum2[t] = 0.f; g_sq2[t] = 0.f; }
}

// ---------------- FPS: 16 blocks x 1024 threads, 4 pts/thread --------------
extern "C" __global__ __launch_bounds__(1024)
void fps_kernel(const float* __restrict__ xyz, float* __restrict__ out_xyz) {
    extern __shared__ float fsh[];
    float* sx = fsh;
    float* sy = fsh + NN;
    float* sz = fsh + 2 * NN;
    unsigned long long* sred = (unsigned long long*)(fsh + 3 * NN);

    int b = blockIdx.x, t = threadIdx.x, lane = t & 31, warp = t >> 5;
    const float* xb = xyz + (size_t)b * 3 * NN;

    float px[4], py[4], pz[4], dist[4];
#pragma unroll
    for (int k = 0; k < 4; k++) {
        int i = t + k * 1024;
        float x = xb[i], y = xb[NN + i], z = xb[2 * NN + i];
        px[k] = x; py[k] = y; pz[k] = z;
        sx[i] = x; sy[i] = y; sz[i] = z;
        dist[k] = 1e10f;
    }
    __syncthreads();

    int far = 0;
    for (int s = 0; s < SS; s++) {
        float cx = sx[far], cy = sy[far], cz = sz[far];
        if (t == 0) {
            out_xyz[(b * 3 + 0) * SS + s] = cx;
            out_xyz[(b * 3 + 1) * SS + s] = cy;
            out_xyz[(b * 3 + 2) * SS + s] = cz;
        }
        float bv; int bi;
        {
            float dx = px[0]-cx, dy = py[0]-cy, dz = pz[0]-cz;
            float d = dx*dx + dy*dy + dz*dz;
            float nd = fminf(dist[0], d); dist[0] = nd;
            bv = nd; bi = t;
        }
#pragma unroll
        for (int k = 1; k < 4; k++) {
            float dx = px[k]-cx, dy = py[k]-cy, dz = pz[k]-cz;
            float d = dx*dx + dy*dy + dz*dz;
            float nd = fminf(dist[k], d); dist[k] = nd;
            if (nd > bv) { bv = nd; bi = t + k * 1024; }
        }
        unsigned uv = __float_as_uint(bv);
        unsigned wm = __reduce_max_sync(0xffffffffu, uv);
        unsigned cand = (uv == wm) ? (unsigned)bi : 0xffffffffu;
        unsigned wi = __reduce_min_sync(0xffffffffu, cand);
        if (lane == 0)
            sred[(s & 1) * 32 + warp] = ((unsigned long long)wm << 32) | wi;
        __syncthreads();
        unsigned long long e = sred[(s & 1) * 32 + lane];
        unsigned v = (unsigned)(e >> 32), ix = (unsigned)e;
        unsigned m2 = __reduce_max_sync(0xffffffffu, v);
        unsigned c2 = (v == m2) ? ix : 0xffffffffu;
        far = (int)__reduce_min_sync(0xffffffffu, c2);
    }
}

// ---------------- ball query + fused layer0 (pos-major out) ----------------
#define BALL_SMEM_F (7*NN + 384 + 32*32*6 + 32*27)
extern "C" __global__ __launch_bounds__(1024)
void ball_kernel(const float* __restrict__ xyz, const float* __restrict__ pts,
                 const float* __restrict__ new_xyz, const float* __restrict__ w0) {
    extern __shared__ float sh[];
    float* sx   = sh;
    float* sy   = sh + NN;
    float* sz   = sh + 2 * NN;
    float* spp  = sh + 3 * NN;
    float* sp0  = sh + 4 * NN;
    float* sp1  = sh + 5 * NN;
    float* sp2  = sh + 6 * NN;
    float* sw   = sh + 7 * NN;
    float* swf  = sw + 384;
    float* sred = swf + 32 * 32 * 6;

    int b = blockIdx.x, chunk = blockIdx.y;
    int t = threadIdx.x;
    const float* xb = xyz + (size_t)b * 3 * NN;
    const float* pb = pts + (size_t)b * 3 * NN;

    if (t < 384) sw[t] = w0[t];
    for (int i = t; i < NN; i += 1024) {
        float x = xb[i], y = xb[NN + i], z = xb[2 * NN + i];
        sx[i] = x; sy[i] = y; sz[i] = z;
        spp[i] = x * x + y * y + z * z;
        sp0[i] = pb[i]; sp1[i] = pb[NN + i]; sp2[i] = pb[2 * NN + i];
    }
    __syncthreads();

    int lane = t & 31, warp = t >> 5;
    float* wslots = swf + warp * 192;

    float gm[21];
    float fs[6];
#pragma unroll
    for (int k = 0; k < 21; k++) gm[k] = 0.f;
#pragma unroll
    for (int k = 0; k < 6; k++) fs[k] = 0.f;

    float* x0b = g_x0 + (size_t)b * POS * 64;

    for (int q = 0; q < 2; q++) {
        int s = chunk * 64 + q * 32 + warp;
        float cx = new_xyz[(b * 3 + 0) * SS + s];
        float cy = new_xyz[(b * 3 + 1) * SS + s];
        float cz = new_xyz[(b * 3 + 2) * SS + s];
        float cc = cx * cx + cy * cy + cz * cz;

        int count = 0;
        int first_i = 0;
        for (int base = 0; base < NN; base += 32) {
            int i = base + lane;
            float dot = cx * sx[i] + cy * sy[i] + cz * sz[i];
            float sum2 = __fadd_rn(cc, spp[i]);
            float sqr = __fsub_rn(sum2, 2.0f * dot);
            bool pred = (sqr <= R2);
            unsigned mask = __ballot_sync(0xffffffffu, pred);
            if (count == 0 && mask) {
                int src = __ffs(mask) - 1;
                first_i = __shfl_sync(0xffffffffu, i, src);
            }
            int rank = __popc(mask & ((1u << lane) - 1u));
            int slot = count + rank;
            if (pred && slot < NSAMP) {
                float* d = wslots + slot * 6;
                d[0] = sx[i] - cx; d[1] = sy[i] - cy; d[2] = sz[i] - cz;
                d[3] = sp0[i];     d[4] = sp1[i];     d[5] = sp2[i];
            }
            count += __popc(mask);
            if (count >= NSAMP) break;
        }
        if (count < NSAMP && lane >= count) {
            int i = first_i;
            float* d = wslots + lane * 6;
            d[0] = sx[i] - cx; d[1] = sy[i] - cy; d[2] = sz[i] - cz;
            d[3] = sp0[i];     d[4] = sp1[i];     d[5] = sp2[i];
        }
        __syncwarp();

        float f[6];
#pragma unroll
        for (int c = 0; c < 6; c++) f[c] = wslots[lane * 6 + c];
        {
            int k = 0;
#pragma unroll
            for (int c = 0; c < 6; c++) {
                fs[c] += f[c];
#pragma unroll
                for (int d = c; d < 6; d++) gm[k++] += f[c] * f[d];
            }
        }
        float* xo = x0b + ((size_t)s * 32 + lane) * 64;
#pragma unroll 4
        for (int o4 = 0; o4 < 16; o4++) {
            float4 r;
            float* rr = (float*)&r;
#pragma unroll
            for (int jj = 0; jj < 4; jj++) {
                int o = o4 * 4 + jj;
                const float2* wr = (const float2*)&sw[o * 6];
                float2 w01 = wr[0], w23 = wr[1], w45 = wr[2];
                rr[jj] = w01.x * f[0] + w01.y * f[1] + w23.x * f[2]
                       + w23.y * f[3] + w45.x * f[4] + w45.y * f[5];
            }
            *(float4*)&xo[o4 * 4] = r;
        }
        __syncwarp();
    }

#pragma unroll
    for (int k = 0; k < 21; k++)
#pragma unroll
        for (int off = 16; off; off >>= 1)
            gm[k] += __shfl_xor_sync(0xffffffffu, gm[k], off);
#pragma unroll
    for (int k = 0; k < 6; k++)
#pragma unroll
        for (int off = 16; off; off >>= 1)
            fs[k] += __shfl_xor_sync(0xffffffffu, fs[k], off);
    if (lane == 0) {
#pragma unroll
        for (int k = 0; k < 21; k++) sred[warp * 27 + k] = gm[k];
#pragma unroll
        for (int k = 0; k < 6; k++)  sred[warp * 27 + 21 + k] = fs[k];
    }
    __syncthreads();
    if (t < 27) {
        float v = 0.f;
#pragma unroll 8
        for (int w = 0; w < 32; w++) v += sred[w * 27 + t];
        if (t < 21) atomicAdd(&g_gm[t], v);
        else        atomicAdd(&g_fs[t - 21], v);
    }
}

// ---------------- finalize0 (analytic) -------------------------------------
__global__ void finalize0_kernel(const float* __restrict__ w0,
                                 const float* __restrict__ g0,
                                 const float* __restrict__ beta0) {
    __shared__ float G[36];
    __shared__ float F[6];
    int t = threadIdx.x;
    if (t < 36) {
        int c = t / 6, d = t % 6;
        int a = min(c, d), e = max(c, d);
        int k = a * 6 - a * (a + 1) / 2 + e;
        G[t] = g_gm[k];
    }
    if (t < 6) F[t] = g_fs[t];
    __syncthreads();
    if (t < 64) {
        float wv[6];
#pragma unroll
        for (int c = 0; c < 6; c++) wv[c] = w0[t * 6 + c];
        const float invP = 1.0f / (float)PTOT;
        float m = 0.f;
#pragma unroll
        for (int c = 0; c < 6; c++) m += wv[c] * F[c];
        m *= invP;
        float e2 = 0.f;
#pragma unroll
        for (int c = 0; c < 6; c++)
#pragma unroll
            for (int d = 0; d < 6; d++) e2 += wv[c] * wv[d] * G[c * 6 + d];
        e2 *= invP;
        float var = e2 - m * m;
        float a = g0[t] * rsqrtf(var + 1e-5f);
        g_a0[t] = a;
        g_c0[t] = beta0[t] - a * m;
    }
}

// ---------------- tf32 mma.sync layer kernels ------------------------------
// Warp tile: 32 pos (2 m-tiles of m16) x 64 out (8 n-tiles of n8), K=64 (8 k8).
// L=1: CTA = 256 pos x 64 out (8 warps on pos). writes x1 pos-major + stats.
// L=2: CTA = 128 pos x 128 out (4 pos-blocks x 2 out-blocks). fused pool+stats.
// smem: sy [TP][68] tf32, sw [COUT][68] tf32, sred_s/sred_q [8][64].
template <int L>
__global__ __launch_bounds__(256) void mma_layer_kernel(const float* __restrict__ w) {
    constexpr int TP   = (L == 1) ? 256 : 128;
    constexpr int COUT = (L == 1) ? 64 : 128;

    extern __shared__ uint32_t dsm[];
    uint32_t* sy = dsm;                         // [TP][68]
    uint32_t* sw = dsm + TP * 68;               // [COUT][68]
    float* sred_s = (float*)(sw + COUT * 68);   // [8][64]
    float* sred_q = sred_s + 8 * 64;            // [8][64]
    __shared__ float san[64], scn[64];

    int t = threadIdx.x;
    int warp = t >> 5, lane = t & 31;
    int gid = lane >> 2, tig = lane & 3;

    int b, p0;
    if (L == 1) { b = blockIdx.x >> 6; p0 = (blockIdx.x & 63) * 256; }
    else        { b = blockIdx.x >> 7; p0 = (blockIdx.x & 127) * 128; }

    int pos_block = (L == 1) ? warp * 32 : (warp >> 1) * 32;
    int ob        = (L == 1) ? 0 : (warp & 1) * 64;

    if (t < 64) {
        san[t] = (L == 1) ? g_a0[t] : g_a1[t];
        scn[t] = (L == 1) ? g_c0[t] : g_c1[t];
    }

    // stage W [COUT][64] -> sw[n*68+k] tf32
    for (int e = t; e < COUT * 64; e += 256) {
        int n = e >> 6, k = e & 63;
        sw[n * 68 + k] = cvt_tf32(w[e]);
    }

    // stage Y: BN + relu + tf32 into sy[row*68+c]
    const float* xin = ((L == 1) ? g_x0 : g_x1) + (size_t)b * POS * 64;
    for (int e = t; e < TP * 16; e += 256) {
        int row = e >> 4, q = e & 15;
        float4 v = ((const float4*)(xin + (size_t)(p0 + row) * 64))[q];
        int c = q * 4;
        uint4 u;
        u.x = cvt_tf32(fmaxf(0.f, san[c+0] * v.x + scn[c+0]));
        u.y = cvt_tf32(fmaxf(0.f, san[c+1] * v.y + scn[c+1]));
        u.z = cvt_tf32(fmaxf(0.f, san[c+2] * v.z + scn[c+2]));
        u.w = cvt_tf32(fmaxf(0.f, san[c+3] * v.w + scn[c+3]));
        *(uint4*)&sy[row * 68 + c] = u;
    }
    __syncthreads();

    float acc[2][8][4];
#pragma unroll
    for (int mt = 0; mt < 2; mt++)
#pragma unroll
        for (int nt = 0; nt < 8; nt++)
#pragma unroll
            for (int k = 0; k < 4; k++) acc[mt][nt][k] = 0.f;

#pragma unroll
    for (int ks = 0; ks < 8; ks++) {
        int k0 = ks * 8;
        uint32_t bfr[8][2];
#pragma unroll
        for (int nt = 0; nt < 8; nt++) {
            int n = ob + nt * 8 + gid;
            bfr[nt][0] = sw[n * 68 + k0 + tig];
            bfr[nt][1] = sw[n * 68 + k0 + tig + 4];
        }
        uint32_t afr[2][4];
#pragma unroll
        for (int mt = 0; mt < 2; mt++) {
            int r = pos_block + mt * 16 + gid;
            afr[mt][0] = sy[r * 68 + k0 + tig];
            afr[mt][1] = sy[(r + 8) * 68 + k0 + tig];
            afr[mt][2] = sy[r * 68 + k0 + tig + 4];
            afr[mt][3] = sy[(r + 8) * 68 + k0 + tig + 4];
        }
#pragma unroll
        for (int mt = 0; mt < 2; mt++)
#pragma unroll
            for (int nt = 0; nt < 8; nt++)
                mma_tf32(acc[mt][nt], afr[mt], bfr[nt]);
    }

    // ---------------- epilogue ----------------
    float* xout = g_x1 + (size_t)b * POS * 64;
    int sg = (p0 + pos_block) >> 5;       // layer2: s index of this warp's group

#pragma unroll
    for (int nt = 0; nt < 8; nt++) {
        float se = 0.f, so = 0.f, qe = 0.f, qo = 0.f;
        float mxe = -1e30f, mxo = -1e30f, mne = 1e30f, mno = 1e30f;
#pragma unroll
        for (int mt = 0; mt < 2; mt++) {
            float v0 = acc[mt][nt][0], v1 = acc[mt][nt][1];
            float v2 = acc[mt][nt][2], v3 = acc[mt][nt][3];
            se += v0 + v2; so += v1 + v3;
            qe += v0*v0 + v2*v2; qo += v1*v1 + v3*v3;
            if (L == 1) {
                int r0 = p0 + pos_block + mt * 16 + gid;
                *(float2*)&xout[(size_t)r0 * 64 + nt * 8 + 2 * tig] =
                    make_float2(v0, v1);
                *(float2*)&xout[(size_t)(r0 + 8) * 64 + nt * 8 + 2 * tig] =
                    make_float2(v2, v3);
            } else {
                mxe = fmaxf(mxe, fmaxf(v0, v2)); mne = fminf(mne, fminf(v0, v2));
                mxo = fmaxf(mxo, fmaxf(v1, v3)); mno = fminf(mno, fminf(v1, v3));
            }
        }
#pragma unroll
        for (int off = 4; off < 32; off <<= 1) {
            se += __shfl_xor_sync(0xffffffffu, se, off);
            so += __shfl_xor_sync(0xffffffffu, so, off);
            qe += __shfl_xor_sync(0xffffffffu, qe, off);
            qo += __shfl_xor_sync(0xffffffffu, qo, off);
            if (L == 2) {
                mxe = fmaxf(mxe, __shfl_xor_sync(0xffffffffu, mxe, off));
                mxo = fmaxf(mxo, __shfl_xor_sync(0xffffffffu, mxo, off));
                mne = fminf(mne, __shfl_xor_sync(0xffffffffu, mne, off));
                mno = fminf(mno, __shfl_xor_sync(0xffffffffu, mno, off));
            }
        }
        if (gid == 0) {
            int lc = nt * 8 + 2 * tig;
            sred_s[warp * 64 + lc]     = se;
            sred_s[warp * 64 + lc + 1] = so;
            sred_q[warp * 64 + lc]     = qe;
            sred_q[warp * 64 + lc + 1] = qo;
            if (L == 2) {
                int o = ob + lc;
                g_gmax[(size_t)(b * 128 + o) * SS + sg]     = mxe;
                g_gmax[(size_t)(b * 128 + o + 1) * SS + sg] = mxo;
                g_gmin[(size_t)(b * 128 + o) * SS + sg]     = mne;
                g_gmin[(size_t)(b * 128 + o + 1) * SS + sg] = mno;
            }
        }
    }
    __syncthreads();

    if (L == 1) {
        if (t < 64) {
            float s = 0.f;
#pragma unroll
            for (int w8 = 0; w8 < 8; w8++) s += sred_s[w8 * 64 + t];
            atomicAdd(&g_sum1[t], s);
        } else if (t < 128) {
            int c = t - 64;
            float q = 0.f;
#pragma unroll
            for (int w8 = 0; w8 < 8; w8++) q += sred_q[w8 * 64 + c];
            atomicAdd(&g_sq1[c], q);
        }
    } else {
        if (t < 128) {
            int par = t >> 6, lc = t & 63;
            float s = 0.f;
#pragma unroll
            for (int j = 0; j < 4; j++) s += sred_s[(2 * j + par) * 64 + lc];
            atomicAdd(&g_sum2[t], s);
        } else {
            int c = t - 128;
            int par = c >> 6, lc = c & 63;
            float q = 0.f;
#pragma unroll
            for (int j = 0; j < 4; j++) q += sred_q[(2 * j + par) * 64 + lc];
            atomicAdd(&g_sq2[c], q);
        }
    }
}

// ---------------- finalize (layers 1/2) ------------------------------------
template <int L>
__global__ void finalize_kernel(const float* __restrict__ g, const float* __restrict__ beta) {
    constexpr int C = (L == 2) ? 128 : 64;
    int o = threadIdx.x;
    if (o < C) {
        const float* sum = (L == 1) ? g_sum1 : g_sum2;
        const float* sq  = (L == 1) ? g_sq1  : g_sq2;
        float* a = (L == 1) ? g_a1 : g_a2;
        float* c = (L == 1) ? g_c1 : g_c2;
        const float invP = 1.0f / (float)PTOT;
        float m = sum[o] * invP;
        float v = sq[o] * invP - m * m;
        float av = g[o] * rsqrtf(v + 1e-5f);
        a[o] = av;
        c[o] = beta[o] - m * av;
    }
}

// ---------------- final: affine + relu on pooled raw max/min ---------------
__global__ __launch_bounds__(256) void final_kernel(float* __restrict__ out) {
    int idx = blockIdx.x * 256 + threadIdx.x;   // (b,o,s)
    int o = (idx >> 9) & 127;
    float a = g_a2[o], c = g_c2[o];
    float m = (a >= 0.f) ? g_gmax[idx] : g_gmin[idx];
    out[BB * 3 * SS + idx] = fmaxf(a * m + c, 0.f);
}

// ---------------- launch ----------------------------------------------------
extern "C" void kernel_launch(void* const* d_in, const int* in_sizes, int n_in,
                              void* d_out, int out_size) {
    const float* xyz   = (const float*)d_in[0];
    const float* pts   = (const float*)d_in[1];
    const float* w0    = (const float*)d_in[2];
    const float* g0    = (const float*)d_in[4];
    const float* beta0 = (const float*)d_in[5];
    const float* w1    = (const float*)d_in[6];
    const float* g1    = (const float*)d_in[8];
    const float* beta1 = (const float*)d_in[9];
    const float* w2    = (const float*)d_in[10];
    const float* g2    = (const float*)d_in[12];
    const float* beta2 = (const float*)d_in[13];
    float* out = (float*)d_out;

    const int SMEM_L1 = (256 * 68 + 64 * 68 + 2 * 8 * 64) * 4;   // ~91KB
    const int SMEM_L2 = (128 * 68 + 128 * 68 + 2 * 8 * 64) * 4;  // ~74KB

    cudaFuncSetAttribute(fps_kernel, cudaFuncAttributeMaxDynamicSharedMemorySize,
                         3 * NN * 4 + 512);
    cudaFuncSetAttribute(ball_kernel, cudaFuncAttributeMaxDynamicSharedMemorySize,
                         BALL_SMEM_F * 4);
    cudaFuncSetAttribute(mma_layer_kernel<1>, cudaFuncAttributeMaxDynamicSharedMemorySize,
                         SMEM_L1);
    cudaFuncSetAttribute(mma_layer_kernel<2>, cudaFuncAttributeMaxDynamicSharedMemorySize,
                         SMEM_L2);

    zero_stats_kernel<<<1, 128>>>();
    fps_kernel<<<BB, 1024, 3 * NN * 4 + 512>>>(xyz, out);
    ball_kernel<<<dim3(BB, 8), 1024, BALL_SMEM_F * 4>>>(xyz, pts, out, w0);
    finalize0_kernel<<<1, 64>>>(w0, g0, beta0);

    mma_layer_kernel<1><<<BB * (POS / 256), 256, SMEM_L1>>>(w1);
    finalize_kernel<1><<<1, 64>>>(g1, beta1);
    mma_layer_kernel<2><<<BB * (POS / 128), 256, SMEM_L2>>>(w2);
    finalize_kernel<2><<<1, 128>>>(g2, beta2);

    final_kernel<<<(BB * 128 * SS) / 256, 256>>>(out);
}

// round 11
// speedup vs baseline: 2.6951x; 1.2855x over previous
#include <cuda_runtime.h>
#include <cuda_fp16.h>
#include <cstdint>

#define BB 16
#define NN 4096
#define SS 512
#define NSAMP 32
#define POS (NSAMP*SS)       // 16384 positions per batch; pos = s*32 + ns
#define PTOT (BB*POS)
#define R2 0.16f

// ---------------- scratch (device globals; no allocation allowed) ----------
__device__ __half2 g_x0h[BB*POS*32];        // [b][pos][32 half2] raw W0*feat
__device__ __half2 g_x1h[BB*POS*32];        // [b][pos][32 half2] raw W1*y1
__device__ float g_gmax[BB*128*SS];         // [b][o][s]
__device__ float g_gmin[BB*128*SS];
__device__ float g_fs[6], g_gm[21];
__device__ float g_sum1[64], g_sq1[64];
__device__ float g_sum2[128], g_sq2[128];

// ---------------- helpers ---------------------------------------------------
__device__ __forceinline__ uint32_t smem_u32(const void* p) {
    return (uint32_t)__cvta_generic_to_shared(p);
}
__device__ __forceinline__ void mma_f16(float d[4], const uint32_t a[4],
                                        uint32_t b0, uint32_t b1) {
    asm volatile(
        "mma.sync.aligned.m16n8k16.row.col.f32.f16.f16.f32 "
        "{%0,%1,%2,%3}, {%4,%5,%6,%7}, {%8,%9}, {%0,%1,%2,%3};"
        : "+f"(d[0]), "+f"(d[1]), "+f"(d[2]), "+f"(d[3])
        : "r"(a[0]), "r"(a[1]), "r"(a[2]), "r"(a[3]), "r"(b0), "r"(b1));
}
#define LDSM_X4(r0,r1,r2,r3,addr) \
    asm volatile("ldmatrix.sync.aligned.m8n8.x4.shared.b16 {%0,%1,%2,%3}, [%4];" \
        : "=r"(r0), "=r"(r1), "=r"(r2), "=r"(r3) : "r"(addr))
#define LDSM_X2(r0,r1,addr) \
    asm volatile("ldmatrix.sync.aligned.m8n8.x2.shared.b16 {%0,%1}, [%2];" \
        : "=r"(r0), "=r"(r1) : "r"(addr))

// ---------------- FPS (+ stats zeroing; deferred centroid writes) ----------
// smem layout: xyz (3*NN floats) | sred 512B ([2][32] u64) | sfarh [512] int
extern "C" __global__ __launch_bounds__(1024)
void fps_kernel(const float* __restrict__ xyz, float* __restrict__ out_xyz) {
    extern __shared__ float fsh[];
    float* sx = fsh;
    float* sy = fsh + NN;
    float* sz = fsh + 2 * NN;
    unsigned long long* sred = (unsigned long long*)(fsh + 3 * NN); // [2][32]=512B
    int* sfarh = (int*)(fsh + 3 * NN + 128);                        // after 512B

    int b = blockIdx.x, t = threadIdx.x, lane = t & 31, warp = t >> 5;
    const float* xb = xyz + (size_t)b * 3 * NN;

    // graph replay: reset global stats accumulators (block 0 only)
    if (b == 0) {
        if (t < 21) g_gm[t] = 0.f;
        else if (t < 27) g_fs[t - 21] = 0.f;
        if (t < 64) { g_sum1[t] = 0.f; g_sq1[t] = 0.f; }
        if (t < 128){ g_sum2[t] = 0.f; g_sq2[t] = 0.f; }
    }

    float px[4], py[4], pz[4], dist[4];
#pragma unroll
    for (int k = 0; k < 4; k++) {
        int i = t + k * 1024;
        float x = xb[i], y = xb[NN + i], z = xb[2 * NN + i];
        px[k] = x; py[k] = y; pz[k] = z;
        sx[i] = x; sy[i] = y; sz[i] = z;
        dist[k] = 1e10f;
    }
    __syncthreads();

    int far = 0;
    for (int s = 0; s < SS; s++) {
        if (t == 0) sfarh[s] = far;
        float cx = sx[far], cy = sy[far], cz = sz[far];
        float bv; int bi;
        {
            float dx = px[0]-cx, dy = py[0]-cy, dz = pz[0]-cz;
            float d = dx*dx + dy*dy + dz*dz;
            float nd = fminf(dist[0], d); dist[0] = nd;
            bv = nd; bi = t;
        }
#pragma unroll
        for (int k = 1; k < 4; k++) {
            float dx = px[k]-cx, dy = py[k]-cy, dz = pz[k]-cz;
            float d = dx*dx + dy*dy + dz*dz;
            float nd = fminf(dist[k], d); dist[k] = nd;
            if (nd > bv) { bv = nd; bi = t + k * 1024; }
        }
        unsigned uv = __float_as_uint(bv);
        unsigned wm = __reduce_max_sync(0xffffffffu, uv);
        unsigned cand = (uv == wm) ? (unsigned)bi : 0xffffffffu;
        unsigned wi = __reduce_min_sync(0xffffffffu, cand);
        if (lane == 0)
            sred[(s & 1) * 32 + warp] = ((unsigned long long)wm << 32) | wi;
        __syncthreads();
        unsigned long long e = sred[(s & 1) * 32 + lane];
        unsigned v = (unsigned)(e >> 32), ix = (unsigned)e;
        unsigned m2 = __reduce_max_sync(0xffffffffu, v);
        unsigned c2 = (v == m2) ? ix : 0xffffffffu;
        far = (int)__reduce_min_sync(0xffffffffu, c2);
    }
    __syncthreads();
    if (t < SS) {
        int i = sfarh[t];
        out_xyz[(b * 3 + 0) * SS + t] = sx[i];
        out_xyz[(b * 3 + 1) * SS + t] = sy[i];
        out_xyz[(b * 3 + 2) * SS + t] = sz[i];
    }
}

// ---------------- ball query + fused layer0 (half2 pos-major out) ----------
#define BALL_SMEM_F (7*NN + 384 + 32*32*6 + 32*27)
extern "C" __global__ __launch_bounds__(1024)
void ball_kernel(const float* __restrict__ xyz, const float* __restrict__ pts,
                 const float* __restrict__ new_xyz, const float* __restrict__ w0) {
    extern __shared__ float sh[];
    float* sx   = sh;
    float* sy   = sh + NN;
    float* sz   = sh + 2 * NN;
    float* spp  = sh + 3 * NN;
    float* sp0  = sh + 4 * NN;
    float* sp1  = sh + 5 * NN;
    float* sp2  = sh + 6 * NN;
    float* sw   = sh + 7 * NN;
    float* swf  = sw + 384;
    float* sred = swf + 32 * 32 * 6;

    int b = blockIdx.x, chunk = blockIdx.y;
    int t = threadIdx.x;
    const float* xb = xyz + (size_t)b * 3 * NN;
    const float* pb = pts + (size_t)b * 3 * NN;

    if (t < 384) sw[t] = w0[t];
    for (int i = t; i < NN; i += 1024) {
        float x = xb[i], y = xb[NN + i], z = xb[2 * NN + i];
        sx[i] = x; sy[i] = y; sz[i] = z;
        spp[i] = x * x + y * y + z * z;
        sp0[i] = pb[i]; sp1[i] = pb[NN + i]; sp2[i] = pb[2 * NN + i];
    }
    __syncthreads();

    int lane = t & 31, warp = t >> 5;
    float* wslots = swf + warp * 192;

    float gm[21];
    float fs[6];
#pragma unroll
    for (int k = 0; k < 21; k++) gm[k] = 0.f;
#pragma unroll
    for (int k = 0; k < 6; k++) fs[k] = 0.f;

    __half2* x0b = g_x0h + (size_t)b * POS * 32;

    for (int q = 0; q < 2; q++) {
        int s = chunk * 64 + q * 32 + warp;
        float cx = new_xyz[(b * 3 + 0) * SS + s];
        float cy = new_xyz[(b * 3 + 1) * SS + s];
        float cz = new_xyz[(b * 3 + 2) * SS + s];
        float cc = cx * cx + cy * cy + cz * cz;

        int count = 0;
        int first_i = 0;
        for (int base = 0; base < NN; base += 32) {
            int i = base + lane;
            float dot = cx * sx[i] + cy * sy[i] + cz * sz[i];
            float sum2 = __fadd_rn(cc, spp[i]);
            float sqr = __fsub_rn(sum2, 2.0f * dot);
            bool pred = (sqr <= R2);
            unsigned mask = __ballot_sync(0xffffffffu, pred);
            if (count == 0 && mask) {
                int src = __ffs(mask) - 1;
                first_i = __shfl_sync(0xffffffffu, i, src);
            }
            int rank = __popc(mask & ((1u << lane) - 1u));
            int slot = count + rank;
            if (pred && slot < NSAMP) {
                float* d = wslots + slot * 6;
                d[0] = sx[i] - cx; d[1] = sy[i] - cy; d[2] = sz[i] - cz;
                d[3] = sp0[i];     d[4] = sp1[i];     d[5] = sp2[i];
            }
            count += __popc(mask);
            if (count >= NSAMP) break;
        }
        if (count < NSAMP && lane >= count) {
            int i = first_i;
            float* d = wslots + lane * 6;
            d[0] = sx[i] - cx; d[1] = sy[i] - cy; d[2] = sz[i] - cz;
            d[3] = sp0[i];     d[4] = sp1[i];     d[5] = sp2[i];
        }
        __syncwarp();

        float f[6];
#pragma unroll
        for (int c = 0; c < 6; c++) f[c] = wslots[lane * 6 + c];
        {
            int k = 0;
#pragma unroll
            for (int c = 0; c < 6; c++) {
                fs[c] += f[c];
#pragma unroll
                for (int d = c; d < 6; d++) gm[k++] += f[c] * f[d];
            }
        }
        __half2* xo = x0b + ((size_t)s * 32 + lane) * 32;
#pragma unroll 2
        for (int j = 0; j < 8; j++) {
            float v[8];
#pragma unroll
            for (int jj = 0; jj < 8; jj++) {
                int o = j * 8 + jj;
                const float2* wr = (const float2*)&sw[o * 6];
                float2 w01 = wr[0], w23 = wr[1], w45 = wr[2];
                v[jj] = w01.x * f[0] + w01.y * f[1] + w23.x * f[2]
                      + w23.y * f[3] + w45.x * f[4] + w45.y * f[5];
            }
            uint4 u;
            uint32_t* up = (uint32_t*)&u;
#pragma unroll
            for (int i = 0; i < 4; i++) {
                __half2 h = __floats2half2_rn(v[2*i], v[2*i+1]);
                up[i] = *(uint32_t*)&h;
            }
            *(uint4*)&xo[j * 4] = u;
        }
        __syncwarp();
    }

#pragma unroll
    for (int k = 0; k < 21; k++)
#pragma unroll
        for (int off = 16; off; off >>= 1)
            gm[k] += __shfl_xor_sync(0xffffffffu, gm[k], off);
#pragma unroll
    for (int k = 0; k < 6; k++)
#pragma unroll
        for (int off = 16; off; off >>= 1)
            fs[k] += __shfl_xor_sync(0xffffffffu, fs[k], off);
    if (lane == 0) {
#pragma unroll
        for (int k = 0; k < 21; k++) sred[warp * 27 + k] = gm[k];
#pragma unroll
        for (int k = 0; k < 6; k++)  sred[warp * 27 + 21 + k] = fs[k];
    }
    __syncthreads();
    if (t < 27) {
        float v = 0.f;
#pragma unroll 8
        for (int w = 0; w < 32; w++) v += sred[w * 27 + t];
        if (t < 21) atomicAdd(&g_gm[t], v);
        else        atomicAdd(&g_fs[t - 21], v);
    }
}

// ---------------- fp16 mma.sync layer kernels (fused finalize prologue) ----
// Warp tile: 32 pos (2 m16) x 64 out (8 n8), K=64 (4 k16 steps via ldmatrix).
// L=1: CTA 256 pos x 64 out; computes BN0 from Gram analytically in-block.
// L=2: CTA 128 pos x 128 out; computes BN1 from g_sum1/g_sq1; fused pool.
template <int L>
__global__ __launch_bounds__(256) void mma_layer_kernel(
    const float* __restrict__ w,       // w1 (L=1) or w2 (L=2): [COUT][64]
    const float* __restrict__ w0,      // L=1 only (Gram matvec)
    const float* __restrict__ gg,      // g0 / g1
    const float* __restrict__ gbeta)   // beta0 / beta1
{
    constexpr int TP   = (L == 1) ? 256 : 128;
    constexpr int COUT = (L == 1) ? 64 : 128;

    extern __shared__ __align__(16) char dsmc[];
    __half* sy = (__half*)dsmc;                          // [TP][72]
    __half* sw = (__half*)(dsmc + TP * 144);             // [COUT][72]
    float* sred_s = (float*)(dsmc + TP * 144 + COUT * 144);  // [8][64]
    float* sred_q = sred_s + 8 * 64;                          // [8][64]
    __shared__ float san[64], scn[64];

    int t = threadIdx.x;
    int warp = t >> 5, lane = t & 31;
    int gid = lane >> 2, tig = lane & 3;

    int b, p0;
    if (L == 1) { b = blockIdx.x >> 6; p0 = (blockIdx.x & 63) * 256; }
    else        { b = blockIdx.x >> 7; p0 = (blockIdx.x & 127) * 128; }
    int pos_block = (L == 1) ? warp * 32 : (warp >> 1) * 32;
    int ob        = (L == 1) ? 0 : (warp & 1) * 64;

    // stage W -> half smem [n][72]
    for (int e = t; e < COUT * 8; e += 256) {
        int n = e >> 3, q = e & 7;
        const float4* wr = (const float4*)(w + n * 64 + q * 8);
        float4 wa = wr[0], wb = wr[1];
        uint4 u;
        uint32_t* up = (uint32_t*)&u;
        __half2 h0 = __floats2half2_rn(wa.x, wa.y); up[0] = *(uint32_t*)&h0;
        __half2 h1 = __floats2half2_rn(wa.z, wa.w); up[1] = *(uint32_t*)&h1;
        __half2 h2 = __floats2half2_rn(wb.x, wb.y); up[2] = *(uint32_t*)&h2;
        __half2 h3 = __floats2half2_rn(wb.z, wb.w); up[3] = *(uint32_t*)&h3;
        *(uint4*)&sw[n * 72 + q * 8] = u;
    }

    // fused finalize of previous layer's BN -> san/scn
    const float invP = 1.0f / (float)PTOT;
    if (t < 64) {
        float m, var;
        if (L == 1) {
            float wv[6];
#pragma unroll
            for (int c = 0; c < 6; c++) wv[c] = w0[t * 6 + c];
            m = 0.f;
#pragma unroll
            for (int c = 0; c < 6; c++) m += wv[c] * g_fs[c];
            m *= invP;
            float e2 = 0.f;
            int k = 0;
#pragma unroll
            for (int c = 0; c < 6; c++)
#pragma unroll
                for (int d = c; d < 6; d++) {
                    float gcd = g_gm[k++];
                    e2 += (d == c) ? wv[c] * wv[c] * gcd
                                   : 2.f * wv[c] * wv[d] * gcd;
                }
            e2 *= invP;
            var = e2 - m * m;
        } else {
            m = g_sum1[t] * invP;
            var = g_sq1[t] * invP - m * m;
        }
        float av = gg[t] * rsqrtf(var + 1e-5f);
        san[t] = av;
        scn[t] = gbeta[t] - m * av;
    }
    __syncthreads();

    // stage Y: BN + relu, half -> smem [row][72]
    const __half2* xin = ((L == 1) ? g_x0h : g_x1h) + (size_t)b * POS * 32;
    for (int e = t; e < TP * 8; e += 256) {
        int row = e >> 3, q = e & 7;
        uint4 u = *(const uint4*)(xin + (size_t)(p0 + row) * 32 + q * 4);
        __half2* hp = (__half2*)&u;
        uint4 o;
        uint32_t* op = (uint32_t*)&o;
#pragma unroll
        for (int i = 0; i < 4; i++) {
            float2 f = __half22float2(hp[i]);
            int c = q * 8 + 2 * i;
            f.x = fmaxf(0.f, san[c]   * f.x + scn[c]);
            f.y = fmaxf(0.f, san[c+1] * f.y + scn[c+1]);
            __half2 h = __floats2half2_rn(f.x, f.y);
            op[i] = *(uint32_t*)&h;
        }
        *(uint4*)&sy[row * 72 + q * 8] = o;
    }
    __syncthreads();

    uint32_t sy_b = smem_u32(sy), sw_b = smem_u32(sw);
    float acc[2][8][4];
#pragma unroll
    for (int mt = 0; mt < 2; mt++)
#pragma unroll
        for (int nt = 0; nt < 8; nt++)
#pragma unroll
            for (int k = 0; k < 4; k++) acc[mt][nt][k] = 0.f;

    int a_row  = pos_block + ((lane >> 3) & 1) * 8 + (lane & 7);
    int a_koff = (lane >> 4) * 8;
    int b_row  = ob + (lane & 7);
    int b_koff = ((lane >> 3) & 1) * 8;

#pragma unroll
    for (int ks = 0; ks < 4; ks++) {
        int k0 = ks * 16;
        uint32_t afr[2][4];
#pragma unroll
        for (int mt = 0; mt < 2; mt++) {
            uint32_t addr = sy_b + (uint32_t)(((a_row + mt * 16) * 72 + k0 + a_koff) * 2);
            LDSM_X4(afr[mt][0], afr[mt][1], afr[mt][2], afr[mt][3], addr);
        }
#pragma unroll
        for (int nt = 0; nt < 8; nt++) {
            uint32_t b0, b1;
            uint32_t baddr = sw_b + (uint32_t)(((b_row + nt * 8) * 72 + k0 + b_koff) * 2);
            LDSM_X2(b0, b1, baddr);
#pragma unroll
            for (int mt = 0; mt < 2; mt++)
                mma_f16(acc[mt][nt], afr[mt], b0, b1);
        }
    }

    // ---------------- epilogue ----------------
    __half2* xout = g_x1h + (size_t)b * POS * 32;
    int sg = (p0 + pos_block) >> 5;

#pragma unroll
    for (int nt = 0; nt < 8; nt++) {
        float se = 0.f, so = 0.f, qe = 0.f, qo = 0.f;
        float mxe = -1e30f, mxo = -1e30f, mne = 1e30f, mno = 1e30f;
#pragma unroll
        for (int mt = 0; mt < 2; mt++) {
            float v0 = acc[mt][nt][0], v1 = acc[mt][nt][1];
            float v2 = acc[mt][nt][2], v3 = acc[mt][nt][3];
            se += v0 + v2; so += v1 + v3;
            qe += v0*v0 + v2*v2; qo += v1*v1 + v3*v3;
            if (L == 1) {
                int r0 = p0 + pos_block + mt * 16 + gid;
                xout[(size_t)r0 * 32 + nt * 4 + tig]       = __floats2half2_rn(v0, v1);
                xout[(size_t)(r0 + 8) * 32 + nt * 4 + tig] = __floats2half2_rn(v2, v3);
            } else {
                mxe = fmaxf(mxe, fmaxf(v0, v2)); mne = fminf(mne, fminf(v0, v2));
                mxo = fmaxf(mxo, fmaxf(v1, v3)); mno = fminf(mno, fminf(v1, v3));
            }
        }
#pragma unroll
        for (int off = 4; off < 32; off <<= 1) {
            se += __shfl_xor_sync(0xffffffffu, se, off);
            so += __shfl_xor_sync(0xffffffffu, so, off);
            qe += __shfl_xor_sync(0xffffffffu, qe, off);
            qo += __shfl_xor_sync(0xffffffffu, qo, off);
            if (L == 2) {
                mxe = fmaxf(mxe, __shfl_xor_sync(0xffffffffu, mxe, off));
                mxo = fmaxf(mxo, __shfl_xor_sync(0xffffffffu, mxo, off));
                mne = fminf(mne, __shfl_xor_sync(0xffffffffu, mne, off));
                mno = fminf(mno, __shfl_xor_sync(0xffffffffu, mno, off));
            }
        }
        if (gid == 0) {
            int lc = nt * 8 + 2 * tig;
            sred_s[warp * 64 + lc]     = se;
            sred_s[warp * 64 + lc + 1] = so;
            sred_q[warp * 64 + lc]     = qe;
            sred_q[warp * 64 + lc + 1] = qo;
            if (L == 2) {
                int o = ob + lc;
                g_gmax[(size_t)(b * 128 + o) * SS + sg]     = mxe;
                g_gmax[(size_t)(b * 128 + o + 1) * SS + sg] = mxo;
                g_gmin[(size_t)(b * 128 + o) * SS + sg]     = mne;
                g_gmin[(size_t)(b * 128 + o + 1) * SS + sg] = mno;
            }
        }
    }
    __syncthreads();

    if (L == 1) {
        if (t < 64) {
            float s = 0.f;
#pragma unroll
            for (int w8 = 0; w8 < 8; w8++) s += sred_s[w8 * 64 + t];
            atomicAdd(&g_sum1[t], s);
        } else if (t < 128) {
            int c = t - 64;
            float q = 0.f;
#pragma unroll
            for (int w8 = 0; w8 < 8; w8++) q += sred_q[w8 * 64 + c];
            atomicAdd(&g_sq1[c], q);
        }
    } else {
        if (t < 128) {
            int par = t >> 6, lc = t & 63;
            float s = 0.f;
#pragma unroll
            for (int j = 0; j < 4; j++) s += sred_s[(2 * j + par) * 64 + lc];
            atomicAdd(&g_sum2[t], s);
        } else {
            int c = t - 128;
            int par = c >> 6, lc = c & 63;
            float q = 0.f;
#pragma unroll
            for (int j = 0; j < 4; j++) q += sred_q[(2 * j + par) * 64 + lc];
            atomicAdd(&g_sq2[c], q);
        }
    }
}

// ---------------- final: fused finalize2 + affine + relu on pooled ---------
__global__ __launch_bounds__(256) void final_kernel(float* __restrict__ out,
                                                    const float* __restrict__ g2,
                                                    const float* __restrict__ beta2) {
    int idx = blockIdx.x * 256 + threadIdx.x;   // (b,o,s)
    int o = (idx >> 9) & 127;
    const float invP = 1.0f / (float)PTOT;
    float m = g_sum2[o] * invP;
    float v = g_sq2[o] * invP - m * m;
    float av = g2[o] * rsqrtf(v + 1e-5f);
    float cv = beta2[o] - m * av;
    float mm = (av >= 0.f) ? g_gmax[idx] : g_gmin[idx];
    out[BB * 3 * SS + idx] = fmaxf(av * mm + cv, 0.f);
}

// ---------------- launch ----------------------------------------------------
extern "C" void kernel_launch(void* const* d_in, const int* in_sizes, int n_in,
                              void* d_out, int out_size) {
    const float* xyz   = (const float*)d_in[0];
    const float* pts   = (const float*)d_in[1];
    const float* w0    = (const float*)d_in[2];
    const float* g0    = (const float*)d_in[4];
    const float* beta0 = (const float*)d_in[5];
    const float* w1    = (const float*)d_in[6];
    const float* g1    = (const float*)d_in[8];
    const float* beta1 = (const float*)d_in[9];
    const float* w2    = (const float*)d_in[10];
    const float* g2    = (const float*)d_in[12];
    const float* beta2 = (const float*)d_in[13];
    float* out = (float*)d_out;

    const int FPS_SMEM = 3 * NN * 4 + 512 + SS * 4;
    const int SMEM_L1  = 256 * 144 + 64 * 144 + 2 * 8 * 64 * 4;   // ~50KB
    const int SMEM_L2  = 128 * 144 + 128 * 144 + 2 * 8 * 64 * 4;  // ~41KB

    cudaFuncSetAttribute(fps_kernel, cudaFuncAttributeMaxDynamicSharedMemorySize,
                         FPS_SMEM);
    cudaFuncSetAttribute(ball_kernel, cudaFuncAttributeMaxDynamicSharedMemorySize,
                         BALL_SMEM_F * 4);
    cudaFuncSetAttribute(mma_layer_kernel<1>, cudaFuncAttributeMaxDynamicSharedMemorySize,
                         SMEM_L1);
    cudaFuncSetAttribute(mma_layer_kernel<2>, cudaFuncAttributeMaxDynamicSharedMemorySize,
                         SMEM_L2);

    fps_kernel<<<BB, 1024, FPS_SMEM>>>(xyz, out);
    ball_kernel<<<dim3(BB, 8), 1024, BALL_SMEM_F * 4>>>(xyz, pts, out, w0);
    mma_layer_kernel<1><<<BB * (POS / 256), 256, SMEM_L1>>>(w1, w0, g0, beta0);
    mma_layer_kernel<2><<<BB * (POS / 128), 256, SMEM_L2>>>(w2, w0, g1, beta1);
    final_kernel<<<(BB * 128 * SS) / 256, 256>>>(out, g2, beta2);
}

// round 12
// speedup vs baseline: 2.8416x; 1.0543x over previous
#include <cuda_runtime.h>
#include <cuda_fp16.h>
#include <cstdint>

#define BB 16
#define NN 4096
#define SS 512
#define NSAMP 32
#define POS (NSAMP*SS)       // 16384 positions per batch; pos = s*32 + ns
#define PTOT (BB*POS)
#define R2 0.16f
#define NGRP 512             // POS/32 groups per batch; group g == centroid s

// Fragment layout: [b][g][mt(2)][ks(4)][reg(4)][lane(32)] uint32 (half2)
// element (row-in-group = mt*16 + (reg&1)*8 + lane/4,
//          k = ks*16 + (reg>>1)*8 + (lane%4)*2 + {0,1})
#define FRAG_BATCH (NGRP*2*4*4*32)   // 524288 uint32 per batch

// ---------------- scratch (device globals; no allocation allowed) ----------
__device__ uint32_t g_x0F[BB*FRAG_BATCH];   // raw W0*feat, fragment layout
__device__ uint32_t g_x1F[BB*FRAG_BATCH];   // raw W1*y1,   fragment layout
__device__ float g_gmax[BB*128*SS];         // [b][o][s]
__device__ float g_gmin[BB*128*SS];
__device__ float g_fs[6], g_gm[21];
__device__ float g_sum1[64], g_sq1[64];
__device__ float g_sum2[128], g_sq2[128];

// ---------------- helpers ---------------------------------------------------
__device__ __forceinline__ uint32_t smem_u32(const void* p) {
    return (uint32_t)__cvta_generic_to_shared(p);
}
__device__ __forceinline__ void mma_f16(float d[4], const uint32_t a[4],
                                        uint32_t b0, uint32_t b1) {
    asm volatile(
        "mma.sync.aligned.m16n8k16.row.col.f32.f16.f16.f32 "
        "{%0,%1,%2,%3}, {%4,%5,%6,%7}, {%8,%9}, {%0,%1,%2,%3};"
        : "+f"(d[0]), "+f"(d[1]), "+f"(d[2]), "+f"(d[3])
        : "r"(a[0]), "r"(a[1]), "r"(a[2]), "r"(a[3]), "r"(b0), "r"(b1));
}
#define LDSM_X2(r0,r1,addr) \
    asm volatile("ldmatrix.sync.aligned.m8n8.x2.shared.b16 {%0,%1}, [%2];" \
        : "=r"(r0), "=r"(r1) : "r"(addr))

// ---------------- FPS (+ stats zeroing; deferred centroid writes) ----------
extern "C" __global__ __launch_bounds__(1024)
void fps_kernel(const float* __restrict__ xyz, float* __restrict__ out_xyz) {
    extern __shared__ float fsh[];
    float* sx = fsh;
    float* sy = fsh + NN;
    float* sz = fsh + 2 * NN;
    unsigned long long* sred = (unsigned long long*)(fsh + 3 * NN); // 512B
    int* sfarh = (int*)(fsh + 3 * NN + 128);                        // [512]

    int b = blockIdx.x, t = threadIdx.x, lane = t & 31, warp = t >> 5;
    const float* xb = xyz + (size_t)b * 3 * NN;

    if (b == 0) {
        if (t < 21) g_gm[t] = 0.f;
        else if (t < 27) g_fs[t - 21] = 0.f;
        if (t < 64) { g_sum1[t] = 0.f; g_sq1[t] = 0.f; }
        if (t < 128){ g_sum2[t] = 0.f; g_sq2[t] = 0.f; }
    }

    float px[4], py[4], pz[4], dist[4];
#pragma unroll
    for (int k = 0; k < 4; k++) {
        int i = t + k * 1024;
        float x = xb[i], y = xb[NN + i], z = xb[2 * NN + i];
        px[k] = x; py[k] = y; pz[k] = z;
        sx[i] = x; sy[i] = y; sz[i] = z;
        dist[k] = 1e10f;
    }
    __syncthreads();

    int far = 0;
    for (int s = 0; s < SS; s++) {
        if (t == 0) sfarh[s] = far;
        float cx = sx[far], cy = sy[far], cz = sz[far];
        float bv; int bi;
        {
            float dx = px[0]-cx, dy = py[0]-cy, dz = pz[0]-cz;
            float d = dx*dx + dy*dy + dz*dz;
            float nd = fminf(dist[0], d); dist[0] = nd;
            bv = nd; bi = t;
        }
#pragma unroll
        for (int k = 1; k < 4; k++) {
            float dx = px[k]-cx, dy = py[k]-cy, dz = pz[k]-cz;
            float d = dx*dx + dy*dy + dz*dz;
            float nd = fminf(dist[k], d); dist[k] = nd;
            if (nd > bv) { bv = nd; bi = t + k * 1024; }
        }
        unsigned uv = __float_as_uint(bv);
        unsigned wm = __reduce_max_sync(0xffffffffu, uv);
        unsigned cand = (uv == wm) ? (unsigned)bi : 0xffffffffu;
        unsigned wi = __reduce_min_sync(0xffffffffu, cand);
        if (lane == 0)
            sred[(s & 1) * 32 + warp] = ((unsigned long long)wm << 32) | wi;
        __syncthreads();
        unsigned long long e = sred[(s & 1) * 32 + lane];
        unsigned v = (unsigned)(e >> 32), ix = (unsigned)e;
        unsigned m2 = __reduce_max_sync(0xffffffffu, v);
        unsigned c2 = (v == m2) ? ix : 0xffffffffu;
        far = (int)__reduce_min_sync(0xffffffffu, c2);
    }
    __syncthreads();
    if (t < SS) {
        int i = sfarh[t];
        out_xyz[(b * 3 + 0) * SS + t] = sx[i];
        out_xyz[(b * 3 + 1) * SS + t] = sy[i];
        out_xyz[(b * 3 + 2) * SS + t] = sz[i];
    }
}

// ---------------- ball query + fused layer0 (fragment-layout out) ----------
#define BALL_SMEM_F (7*NN + 384 + 32*32*6 + 32*27)
extern "C" __global__ __launch_bounds__(1024)
void ball_kernel(const float* __restrict__ xyz, const float* __restrict__ pts,
                 const float* __restrict__ new_xyz, const float* __restrict__ w0) {
    extern __shared__ float sh[];
    float* sx   = sh;
    float* sy   = sh + NN;
    float* sz   = sh + 2 * NN;
    float* spp  = sh + 3 * NN;
    float* sp0  = sh + 4 * NN;
    float* sp1  = sh + 5 * NN;
    float* sp2  = sh + 6 * NN;
    float* sw   = sh + 7 * NN;
    float* swf  = sw + 384;
    float* sred = swf + 32 * 32 * 6;

    int b = blockIdx.x, chunk = blockIdx.y;
    int t = threadIdx.x;
    const float* xb = xyz + (size_t)b * 3 * NN;
    const float* pb = pts + (size_t)b * 3 * NN;

    if (t < 384) sw[t] = w0[t];
    for (int i = t; i < NN; i += 1024) {
        float x = xb[i], y = xb[NN + i], z = xb[2 * NN + i];
        sx[i] = x; sy[i] = y; sz[i] = z;
        spp[i] = x * x + y * y + z * z;
        sp0[i] = pb[i]; sp1[i] = pb[NN + i]; sp2[i] = pb[2 * NN + i];
    }
    __syncthreads();

    int lane = t & 31, warp = t >> 5;
    float* wslots = swf + warp * 192;

    float gm[21];
    float fs[6];
#pragma unroll
    for (int k = 0; k < 21; k++) gm[k] = 0.f;
#pragma unroll
    for (int k = 0; k < 6; k++) fs[k] = 0.f;

    uint32_t* x0b = g_x0F + (size_t)b * FRAG_BATCH;
    // fragment coords for this lane (pos-in-group = lane)
    int mt = lane >> 4, gid8 = lane & 7, rh = (lane >> 3) & 1;

    for (int q = 0; q < 2; q++) {
        int s = chunk * 64 + q * 32 + warp;
        float cx = new_xyz[(b * 3 + 0) * SS + s];
        float cy = new_xyz[(b * 3 + 1) * SS + s];
        float cz = new_xyz[(b * 3 + 2) * SS + s];
        float cc = cx * cx + cy * cy + cz * cz;

        int count = 0;
        int first_i = 0;
        for (int base = 0; base < NN; base += 32) {
            int i = base + lane;
            float dot = cx * sx[i] + cy * sy[i] + cz * sz[i];
            float sum2 = __fadd_rn(cc, spp[i]);
            float sqr = __fsub_rn(sum2, 2.0f * dot);
            bool pred = (sqr <= R2);
            unsigned mask = __ballot_sync(0xffffffffu, pred);
            if (count == 0 && mask) {
                int src = __ffs(mask) - 1;
                first_i = __shfl_sync(0xffffffffu, i, src);
            }
            int rank = __popc(mask & ((1u << lane) - 1u));
            int slot = count + rank;
            if (pred && slot < NSAMP) {
                float* d = wslots + slot * 6;
                d[0] = sx[i] - cx; d[1] = sy[i] - cy; d[2] = sz[i] - cz;
                d[3] = sp0[i];     d[4] = sp1[i];     d[5] = sp2[i];
            }
            count += __popc(mask);
            if (count >= NSAMP) break;
        }
        if (count < NSAMP && lane >= count) {
            int i = first_i;
            float* d = wslots + lane * 6;
            d[0] = sx[i] - cx; d[1] = sy[i] - cy; d[2] = sz[i] - cz;
            d[3] = sp0[i];     d[4] = sp1[i];     d[5] = sp2[i];
        }
        __syncwarp();

        float f[6];
#pragma unroll
        for (int c = 0; c < 6; c++) f[c] = wslots[lane * 6 + c];
        {
            int k = 0;
#pragma unroll
            for (int c = 0; c < 6; c++) {
                fs[c] += f[c];
#pragma unroll
                for (int d = c; d < 6; d++) gm[k++] += f[c] * f[d];
            }
        }
        // 8 channel-chunks of 8 -> one uint4 fragment store each
#pragma unroll 2
        for (int jc = 0; jc < 8; jc++) {
            float v[8];
#pragma unroll
            for (int jj = 0; jj < 8; jj++) {
                int o = jc * 8 + jj;
                const float2* wr = (const float2*)&sw[o * 6];
                float2 w01 = wr[0], w23 = wr[1], w45 = wr[2];
                v[jj] = w01.x * f[0] + w01.y * f[1] + w23.x * f[2]
                      + w23.y * f[3] + w45.x * f[4] + w45.y * f[5];
            }
            int ks = jc >> 1, kh = jc & 1;
            uint4 u;
            uint32_t* up = (uint32_t*)&u;
#pragma unroll
            for (int i = 0; i < 4; i++) {
                __half2 h = __floats2half2_rn(v[2*i], v[2*i+1]);
                up[i] = *(uint32_t*)&h;
            }
            size_t idx = ((((size_t)s * 2 + mt) * 4 + ks) * 4 + (kh * 2 + rh)) * 32
                       + gid8 * 4;
            *(uint4*)&x0b[idx] = u;
        }
        __syncwarp();
    }

#pragma unroll
    for (int k = 0; k < 21; k++)
#pragma unroll
        for (int off = 16; off; off >>= 1)
            gm[k] += __shfl_xor_sync(0xffffffffu, gm[k], off);
#pragma unroll
    for (int k = 0; k < 6; k++)
#pragma unroll
        for (int off = 16; off; off >>= 1)
            fs[k] += __shfl_xor_sync(0xffffffffu, fs[k], off);
    if (lane == 0) {
#pragma unroll
        for (int k = 0; k < 21; k++) sred[warp * 27 + k] = gm[k];
#pragma unroll
        for (int k = 0; k < 6; k++)  sred[warp * 27 + 21 + k] = fs[k];
    }
    __syncthreads();
    if (t < 27) {
        float v = 0.f;
#pragma unroll 8
        for (int w = 0; w < 32; w++) v += sred[w * 27 + t];
        if (t < 21) atomicAdd(&g_gm[t], v);
        else        atomicAdd(&g_fs[t - 21], v);
    }
}

// ---------------- fp16 mma.sync layer kernels (fragment A, tile loop) ------
// A fragments loaded straight from global (no smem staging); BN+relu in regs.
// L=1: per tile 8 groups (8 warps x 1), TILES=4. Writes x1F fragments + stats.
// L=2: per tile 4 groups (warp pairs), TILES=8. Fused pool + stats.
template <int L>
__global__ __launch_bounds__(256, 2) void mma_layer_kernel(
    const float* __restrict__ w,       // w1 / w2 : [COUT][64]
    const float* __restrict__ w0,      // L=1 only (Gram matvec)
    const float* __restrict__ gg,      // g0 / g1
    const float* __restrict__ gbeta)   // beta0 / beta1
{
    constexpr int COUT  = (L == 1) ? 64 : 128;
    constexpr int TILES = (L == 1) ? 4 : 8;

    extern __shared__ __align__(16) char dsmc[];
    __half* sw = (__half*)dsmc;                          // [COUT][72]
    float* sred_s = (float*)(dsmc + COUT * 144);         // [8][64]
    float* sred_q = sred_s + 8 * 64;                     // [8][64]
    __shared__ float san[64], scn[64];

    int t = threadIdx.x;
    int warp = t >> 5, lane = t & 31;
    int gid = lane >> 2, tig = lane & 3;

    int b = blockIdx.x >> 4, chunk = blockIdx.x & 15;
    int ob = (L == 1) ? 0 : (warp & 1) * 64;

    // stage W -> half smem [n][72] (once per CTA)
    for (int e = t; e < COUT * 8; e += 256) {
        int n = e >> 3, q = e & 7;
        const float4* wr = (const float4*)(w + n * 64 + q * 8);
        float4 wa = wr[0], wb = wr[1];
        uint4 u;
        uint32_t* up = (uint32_t*)&u;
        __half2 h0 = __floats2half2_rn(wa.x, wa.y); up[0] = *(uint32_t*)&h0;
        __half2 h1 = __floats2half2_rn(wa.z, wa.w); up[1] = *(uint32_t*)&h1;
        __half2 h2 = __floats2half2_rn(wb.x, wb.y); up[2] = *(uint32_t*)&h2;
        __half2 h3 = __floats2half2_rn(wb.z, wb.w); up[3] = *(uint32_t*)&h3;
        *(uint4*)&sw[n * 72 + q * 8] = u;
    }
    // zero stats accumulators
    for (int e = t; e < 512; e += 256) { sred_s[e] = 0.f; sred_q[e] = 0.f; }

    // fused finalize of previous layer's BN -> san/scn
    const float invP = 1.0f / (float)PTOT;
    if (t < 64) {
        float m, var;
        if (L == 1) {
            float wv[6];
#pragma unroll
            for (int c = 0; c < 6; c++) wv[c] = w0[t * 6 + c];
            m = 0.f;
#pragma unroll
            for (int c = 0; c < 6; c++) m += wv[c] * g_fs[c];
            m *= invP;
            float e2 = 0.f;
            int k = 0;
#pragma unroll
            for (int c = 0; c < 6; c++)
#pragma unroll
                for (int d = c; d < 6; d++) {
                    float gcd = g_gm[k++];
                    e2 += (d == c) ? wv[c] * wv[c] * gcd
                                   : 2.f * wv[c] * wv[d] * gcd;
                }
            e2 *= invP;
            var = e2 - m * m;
        } else {
            m = g_sum1[t] * invP;
            var = g_sq1[t] * invP - m * m;
        }
        float av = gg[t] * rsqrtf(var + 1e-5f);
        san[t] = av;
        scn[t] = gbeta[t] - m * av;
    }
    __syncthreads();

    const uint32_t* xin = ((L == 1) ? g_x0F : g_x1F) + (size_t)b * FRAG_BATCH;
    uint32_t* xout = g_x1F + (size_t)b * FRAG_BATCH;
    uint32_t sw_b = smem_u32(sw);
    int b_row  = ob + (lane & 7);
    int b_koff = ((lane >> 3) & 1) * 8;

    for (int tile = 0; tile < TILES; tile++) {
        int g = (L == 1) ? (chunk * 32 + tile * 8 + warp)
                         : (chunk * 32 + tile * 4 + (warp >> 1));

        // ---- load A fragments from global (coalesced 128B lines) ----
        uint32_t afr[2][4][4];
#pragma unroll
        for (int mt = 0; mt < 2; mt++)
#pragma unroll
            for (int ks = 0; ks < 4; ks++) {
                const uint32_t* p = xin + ((((size_t)g * 2 + mt) * 4 + ks) * 4) * 32 + lane;
                afr[mt][ks][0] = p[0];
                afr[mt][ks][1] = p[32];
                afr[mt][ks][2] = p[64];
                afr[mt][ks][3] = p[96];
            }
        // ---- BN + relu in registers ----
#pragma unroll
        for (int mt = 0; mt < 2; mt++)
#pragma unroll
            for (int ks = 0; ks < 4; ks++)
#pragma unroll
                for (int j = 0; j < 4; j++) {
                    int c0 = ks * 16 + (j >> 1) * 8 + tig * 2;
                    __half2 h = *(__half2*)&afr[mt][ks][j];
                    float2 f = __half22float2(h);
                    f.x = fmaxf(0.f, san[c0]     * f.x + scn[c0]);
                    f.y = fmaxf(0.f, san[c0 + 1] * f.y + scn[c0 + 1]);
                    __half2 ho = __floats2half2_rn(f.x, f.y);
                    afr[mt][ks][j] = *(uint32_t*)&ho;
                }

        // ---- MMA ----
        float acc[2][8][4];
#pragma unroll
        for (int mt = 0; mt < 2; mt++)
#pragma unroll
            for (int nt = 0; nt < 8; nt++)
#pragma unroll
                for (int k = 0; k < 4; k++) acc[mt][nt][k] = 0.f;
#pragma unroll
        for (int ks = 0; ks < 4; ks++) {
            int k0 = ks * 16;
#pragma unroll
            for (int nt = 0; nt < 8; nt++) {
                uint32_t b0, b1;
                uint32_t baddr = sw_b + (uint32_t)(((b_row + nt * 8) * 72 + k0 + b_koff) * 2);
                LDSM_X2(b0, b1, baddr);
                mma_f16(acc[0][nt], afr[0][ks], b0, b1);
                mma_f16(acc[1][nt], afr[1][ks], b0, b1);
            }
        }

        // ---- epilogue ----
#pragma unroll
        for (int nt = 0; nt < 8; nt++) {
            float se = 0.f, so = 0.f, qe = 0.f, qo = 0.f;
            float mxe = -1e30f, mxo = -1e30f, mne = 1e30f, mno = 1e30f;
#pragma unroll
            for (int mt = 0; mt < 2; mt++) {
                float v0 = acc[mt][nt][0], v1 = acc[mt][nt][1];
                float v2 = acc[mt][nt][2], v3 = acc[mt][nt][3];
                se += v0 + v2; so += v1 + v3;
                qe += v0*v0 + v2*v2; qo += v1*v1 + v3*v3;
                if (L == 1) {
                    // D fragment == next layer's A fragment (same lane)
                    __half2 h01 = __floats2half2_rn(v0, v1);
                    __half2 h23 = __floats2half2_rn(v2, v3);
                    size_t base = ((((size_t)g * 2 + mt) * 4 + (nt >> 1)) * 4
                                  + (nt & 1) * 2) * 32 + lane;
                    xout[base]      = *(uint32_t*)&h01;
                    xout[base + 32] = *(uint32_t*)&h23;
                } else {
                    mxe = fmaxf(mxe, fmaxf(v0, v2)); mne = fminf(mne, fminf(v0, v2));
                    mxo = fmaxf(mxo, fmaxf(v1, v3)); mno = fminf(mno, fminf(v1, v3));
                }
            }
#pragma unroll
            for (int off = 4; off < 32; off <<= 1) {
                se += __shfl_xor_sync(0xffffffffu, se, off);
                so += __shfl_xor_sync(0xffffffffu, so, off);
                qe += __shfl_xor_sync(0xffffffffu, qe, off);
                qo += __shfl_xor_sync(0xffffffffu, qo, off);
                if (L == 2) {
                    mxe = fmaxf(mxe, __shfl_xor_sync(0xffffffffu, mxe, off));
                    mxo = fmaxf(mxo, __shfl_xor_sync(0xffffffffu, mxo, off));
                    mne = fminf(mne, __shfl_xor_sync(0xffffffffu, mne, off));
                    mno = fminf(mno, __shfl_xor_sync(0xffffffffu, mno, off));
                }
            }
            if (gid == 0) {
                int lc = nt * 8 + 2 * tig;
                sred_s[warp * 64 + lc]     += se;
                sred_s[warp * 64 + lc + 1] += so;
                sred_q[warp * 64 + lc]     += qe;
                sred_q[warp * 64 + lc + 1] += qo;
                if (L == 2) {
                    int o = ob + lc;
                    g_gmax[(size_t)(b * 128 + o) * SS + g]     = mxe;
                    g_gmax[(size_t)(b * 128 + o + 1) * SS + g] = mxo;
                    g_gmin[(size_t)(b * 128 + o) * SS + g]     = mne;
                    g_gmin[(size_t)(b * 128 + o + 1) * SS + g] = mno;
                }
            }
        }
    }
    __syncthreads();

    if (L == 1) {
        if (t < 64) {
            float s = 0.f;
#pragma unroll
            for (int w8 = 0; w8 < 8; w8++) s += sred_s[w8 * 64 + t];
            atomicAdd(&g_sum1[t], s);
        } else if (t < 128) {
            int c = t - 64;
            float q = 0.f;
#pragma unroll
            for (int w8 = 0; w8 < 8; w8++) q += sred_q[w8 * 64 + c];
            atomicAdd(&g_sq1[c], q);
        }
    } else {
        if (t < 128) {
            int par = t >> 6, lc = t & 63;
            float s = 0.f;
#pragma unroll
            for (int j = 0; j < 4; j++) s += sred_s[(2 * j + par) * 64 + lc];
            atomicAdd(&g_sum2[t], s);
        } else {
            int c = t - 128;
            int par = c >> 6, lc = c & 63;
            float q = 0.f;
#pragma unroll
            for (int j = 0; j < 4; j++) q += sred_q[(2 * j + par) * 64 + lc];
            atomicAdd(&g_sq2[c], q);
        }
    }
}

// ---------------- final: fused finalize2 + affine + relu on pooled ---------
__global__ __launch_bounds__(256) void final_kernel(float* __restrict__ out,
                                                    const float* __restrict__ g2,
                                                    const float* __restrict__ beta2) {
    int idx = blockIdx.x * 256 + threadIdx.x;   // (b,o,s)
    int o = (idx >> 9) & 127;
    const float invP = 1.0f / (float)PTOT;
    float m = g_sum2[o] * invP;
    float v = g_sq2[o] * invP - m * m;
    float av = g2[o] * rsqrtf(v + 1e-5f);
    float cv = beta2[o] - m * av;
    float mm = (av >= 0.f) ? g_gmax[idx] : g_gmin[idx];
    out[BB * 3 * SS + idx] = fmaxf(av * mm + cv, 0.f);
}

// ---------------- launch ----------------------------------------------------
extern "C" void kernel_launch(void* const* d_in, const int* in_sizes, int n_in,
                              void* d_out, int out_size) {
    const float* xyz   = (const float*)d_in[0];
    const float* pts   = (const float*)d_in[1];
    const float* w0    = (const float*)d_in[2];
    const float* g0    = (const float*)d_in[4];
    const float* beta0 = (const float*)d_in[5];
    const float* w1    = (const float*)d_in[6];
    const float* g1    = (const float*)d_in[8];
    const float* beta1 = (const float*)d_in[9];
    const float* w2    = (const float*)d_in[10];
    const float* g2    = (const float*)d_in[12];
    const float* beta2 = (const float*)d_in[13];
    float* out = (float*)d_out;

    const int FPS_SMEM = 3 * NN * 4 + 512 + SS * 4;
    const int SMEM_L1  = 64 * 144 + 2 * 8 * 64 * 4;    // ~13.3KB
    const int SMEM_L2  = 128 * 144 + 2 * 8 * 64 * 4;   // ~22.5KB

    cudaFuncSetAttribute(fps_kernel, cudaFuncAttributeMaxDynamicSharedMemorySize,
                         FPS_SMEM);
    cudaFuncSetAttribute(ball_kernel, cudaFuncAttributeMaxDynamicSharedMemorySize,
                         BALL_SMEM_F * 4);
    cudaFuncSetAttribute(mma_layer_kernel<1>, cudaFuncAttributeMaxDynamicSharedMemorySize,
                         SMEM_L1);
    cudaFuncSetAttribute(mma_layer_kernel<2>, cudaFuncAttributeMaxDynamicSharedMemorySize,
                         SMEM_L2);

    fps_kernel<<<BB, 1024, FPS_SMEM>>>(xyz, out);
    ball_kernel<<<dim3(BB, 8), 1024, BALL_SMEM_F * 4>>>(xyz, pts, out, w0);
    mma_layer_kernel<1><<<256, 256, SMEM_L1>>>(w1, w0, g0, beta0);
    mma_layer_kernel<2><<<256, 256, SMEM_L2>>>(w2, w0, g1, beta1);
    final_kernel<<<(BB * 128 * SS) / 256, 256>>>(out, g2, beta2);
}